// round 1
// baseline (speedup 1.0000x reference)
#include <cuda_runtime.h>

#define NN 100000
#define EE 1600000
typedef unsigned long long u64;

// ---------------- device scratch (no allocations allowed) ----------------
__device__ float g_bufA[(size_t)NN * 256];
__device__ float g_bufB[(size_t)NN * 256];
__device__ float g_dno[NN];
__device__ float g_dni[NN];
__device__ int   g_cout[NN];
__device__ int   g_cin[NN];
__device__ int   g_ptr[NN + 1];
__device__ int   g_cur[NN];
__device__ int   g_csrc[EE];

// ---------------- small helpers ----------------
__device__ __forceinline__ u64 pk2(float a, float b) {
    u64 r; asm("mov.b64 %0,{%1,%2};" : "=l"(r) : "f"(a), "f"(b)); return r;
}
__device__ __forceinline__ u64 ffma2(u64 a, u64 b, u64 c) {
    u64 d; asm("fma.rn.f32x2 %0,%1,%2,%3;" : "=l"(d) : "l"(a), "l"(b), "l"(c)); return d;
}
__device__ __forceinline__ void upk2(u64 p, float& a, float& b) {
    asm("mov.b64 {%0,%1},%2;" : "=f"(a), "=f"(b) : "l"(p));
}
__device__ __forceinline__ void fma4(float4& a, float w, const float4 v) {
    a.x = fmaf(w, v.x, a.x); a.y = fmaf(w, v.y, a.y);
    a.z = fmaf(w, v.z, a.z); a.w = fmaf(w, v.w, a.w);
}

// ---------------- prep kernels ----------------
__global__ void k_zero() {
    int i = blockIdx.x * blockDim.x + threadIdx.x;
    if (i < NN) { g_cout[i] = 0; g_cin[i] = 0; }
}

__global__ void k_deg(const int* __restrict__ src, const int* __restrict__ dst) {
    int i = blockIdx.x * blockDim.x + threadIdx.x;
    if (i < EE) {
        atomicAdd(&g_cout[src[i]], 1);
        atomicAdd(&g_cin[dst[i]], 1);
    }
}

__global__ void k_norm() {
    int i = blockIdx.x * blockDim.x + threadIdx.x;
    if (i < NN) {
        int co = g_cout[i]; if (co < 1) co = 1;
        int ci = g_cin[i];  if (ci < 1) ci = 1;
        g_dno[i] = rsqrtf((float)co);
        g_dni[i] = rsqrtf((float)ci);
    }
}

// single-block exclusive scan of g_cin -> g_ptr, g_cur ; g_ptr[NN] = E
__global__ void k_scan() {
    __shared__ int ws[32];
    const int tid = threadIdx.x;
    const int lane = tid & 31, wid = tid >> 5;
    int carry = 0;
    for (int base = 0; base < NN; base += 1024) {
        int i = base + tid;
        int v = (i < NN) ? g_cin[i] : 0;
        int x = v;
        #pragma unroll
        for (int o = 1; o < 32; o <<= 1) {
            int t = __shfl_up_sync(0xffffffffu, x, o);
            if (lane >= o) x += t;
        }
        if (lane == 31) ws[wid] = x;
        __syncthreads();
        if (wid == 0) {
            int s = ws[lane];
            #pragma unroll
            for (int o = 1; o < 32; o <<= 1) {
                int t = __shfl_up_sync(0xffffffffu, s, o);
                if (lane >= o) s += t;
            }
            ws[lane] = s;
        }
        __syncthreads();
        int pre = (wid > 0) ? ws[wid - 1] : 0;
        int exc = carry + pre + x - v;
        if (i < NN) { g_ptr[i] = exc; g_cur[i] = exc; }
        carry += ws[31];
        __syncthreads();
    }
    if (tid == 0) g_ptr[NN] = carry;
}

__global__ void k_fill(const int* __restrict__ src, const int* __restrict__ dst) {
    int i = blockIdx.x * blockDim.x + threadIdx.x;
    if (i < EE) {
        int d = dst[i];
        int p = atomicAdd(&g_cur[d], 1);
        g_csrc[p] = src[i];
    }
}

// ---------------- aggregation: warp-per-node over CSR ----------------
// out[n] = sum_{e in csr(n)} dno[src_e] * in[src_e]   (EPI: out=(acc+b3)*dni[n])
template<int D, bool EPI>
__global__ void k_agg(const float* __restrict__ in, float* __restrict__ out,
                      const float* __restrict__ b3) {
    const int w = (blockIdx.x << 3) + (threadIdx.x >> 5);  // 8 warps / block
    const int lane = threadIdx.x & 31;
    if (w >= NN) return;
    const int beg = g_ptr[w], end = g_ptr[w + 1];
    float4 a0 = make_float4(0.f, 0.f, 0.f, 0.f);
    float4 a1 = make_float4(0.f, 0.f, 0.f, 0.f);
    const float4* __restrict__ inp = (const float4*)in;

    int e = beg;
    for (; e + 2 <= end; e += 2) {
        int s0 = g_csrc[e], s1 = g_csrc[e + 1];
        float w0 = g_dno[s0], w1 = g_dno[s1];
        const float4* r0 = inp + (size_t)s0 * (D / 4);
        const float4* r1 = inp + (size_t)s1 * (D / 4);
        float4 v0 = r0[lane], v1 = r1[lane];
        fma4(a0, w0, v0); fma4(a0, w1, v1);
        if (D == 256) {
            float4 u0 = r0[lane + 32], u1 = r1[lane + 32];
            fma4(a1, w0, u0); fma4(a1, w1, u1);
        }
    }
    if (e < end) {
        int s0 = g_csrc[e];
        float w0 = g_dno[s0];
        const float4* r0 = inp + (size_t)s0 * (D / 4);
        fma4(a0, w0, r0[lane]);
        if (D == 256) fma4(a1, w0, r0[lane + 32]);
    }
    if (EPI) {
        float4 bb = ((const float4*)b3)[lane];
        float d = g_dni[w];
        a0.x = (a0.x + bb.x) * d; a0.y = (a0.y + bb.y) * d;
        a0.z = (a0.z + bb.z) * d; a0.w = (a0.w + bb.w) * d;
    }
    float4* op = (float4*)out + (size_t)w * (D / 4);
    op[lane] = a0;
    if (D == 256) op[lane + 32] = a1;
}

// ---------------- GEMM (f32x2 FFMA2) + fused bias/deg_in/LN/PReLU ----------------
// C[M,BN] = A[M,K] @ W[K,BN]; ENC: r=(acc+bias)*dni[row]; LN(g,be); PReLU(alpha)
template<int K, int BN, bool ENC>
__global__ void __launch_bounds__(512, 1)
k_gemm(const float* __restrict__ A, const float* __restrict__ W,
       const float* __restrict__ bias, const float* __restrict__ gam,
       const float* __restrict__ bet, const float* __restrict__ alp,
       float* __restrict__ C) {
    constexpr int TX = BN / 8;        // threads along N (8 cols each)
    constexpr int TY = 512 / TX;      // threads along M (8 rows each)
    constexpr int BM = TY * 8;
    constexpr int NT = K / 16;
    constexpr int AP = BM + 4;        // As row pad (bank spread for transpose STS)
    static_assert(!ENC || BN == 256, "ENC epilogue needs full-warp rows");

    __shared__ float As[16][AP];
    __shared__ float Bs[16][BN];

    const int tid = threadIdx.x;
    const int mbase = blockIdx.x * BM;

    // A loader: thread -> (kq in 0..3 float4-within-row, am in 0..127)
    const int kq = tid & 3;
    const int am = tid >> 2;
    constexpr int AC = BM / 128;      // float4 per thread for A
    constexpr int F4R = BN / 4;       // float4 per B row
    const int bf = tid % F4R;
    const int br0 = tid / F4R;
    constexpr int RPS = 512 / F4R;    // B rows covered per step
    constexpr int BC = 16 / RPS;      // float4 per thread for B

    const int tx = tid % TX;
    const int ty = tid / TX;

    float4 ar[AC], brg[BC];
    u64 acc[8][4];
    #pragma unroll
    for (int i = 0; i < 8; i++) {
        #pragma unroll
        for (int j = 0; j < 4; j++) acc[i][j] = 0ull;
    }

    // prefetch tile 0
    #pragma unroll
    for (int c = 0; c < AC; c++) {
        int row = mbase + am + 128 * c; if (row > NN - 1) row = NN - 1;
        ar[c] = *(const float4*)(A + (size_t)row * K + kq * 4);
    }
    #pragma unroll
    for (int c = 0; c < BC; c++) {
        int r = br0 + RPS * c;
        brg[c] = *(const float4*)(W + (size_t)r * BN + bf * 4);
    }

    for (int t = 0;;) {
        __syncthreads();
        #pragma unroll
        for (int c = 0; c < AC; c++) {
            int m = am + 128 * c;
            As[kq * 4 + 0][m] = ar[c].x;
            As[kq * 4 + 1][m] = ar[c].y;
            As[kq * 4 + 2][m] = ar[c].z;
            As[kq * 4 + 3][m] = ar[c].w;
        }
        #pragma unroll
        for (int c = 0; c < BC; c++) {
            int r = br0 + RPS * c;
            *(float4*)&Bs[r][bf * 4] = brg[c];
        }
        __syncthreads();
        if (t + 1 < NT) {  // prefetch next tile under the compute below
            int k0 = (t + 1) * 16;
            #pragma unroll
            for (int c = 0; c < AC; c++) {
                int row = mbase + am + 128 * c; if (row > NN - 1) row = NN - 1;
                ar[c] = *(const float4*)(A + (size_t)row * K + k0 + kq * 4);
            }
            #pragma unroll
            for (int c = 0; c < BC; c++) {
                int r = k0 + br0 + RPS * c;
                brg[c] = *(const float4*)(W + (size_t)r * BN + bf * 4);
            }
        }
        #pragma unroll
        for (int kk = 0; kk < 16; kk++) {
            float4 a0 = *(const float4*)&As[kk][ty * 8];
            float4 a1 = *(const float4*)&As[kk][ty * 8 + 4];
            float4 b0 = *(const float4*)&Bs[kk][tx * 8];
            float4 b1 = *(const float4*)&Bs[kk][tx * 8 + 4];
            u64 pb[4] = { pk2(b0.x, b0.y), pk2(b0.z, b0.w),
                          pk2(b1.x, b1.y), pk2(b1.z, b1.w) };
            float av[8] = { a0.x, a0.y, a0.z, a0.w, a1.x, a1.y, a1.z, a1.w };
            #pragma unroll
            for (int i = 0; i < 8; i++) {
                u64 pa = pk2(av[i], av[i]);
                #pragma unroll
                for (int j = 0; j < 4; j++) acc[i][j] = ffma2(pa, pb[j], acc[i][j]);
            }
        }
        if (++t == NT) break;
    }

    if (ENC) {
        const float alpha = __ldg(alp);
        float biv[8], gav[8], bev[8];
        {
            float4 t0 = *(const float4*)(bias + tx * 8);
            float4 t1 = *(const float4*)(bias + tx * 8 + 4);
            biv[0]=t0.x; biv[1]=t0.y; biv[2]=t0.z; biv[3]=t0.w;
            biv[4]=t1.x; biv[5]=t1.y; biv[6]=t1.z; biv[7]=t1.w;
            t0 = *(const float4*)(gam + tx * 8); t1 = *(const float4*)(gam + tx * 8 + 4);
            gav[0]=t0.x; gav[1]=t0.y; gav[2]=t0.z; gav[3]=t0.w;
            gav[4]=t1.x; gav[5]=t1.y; gav[6]=t1.z; gav[7]=t1.w;
            t0 = *(const float4*)(bet + tx * 8); t1 = *(const float4*)(bet + tx * 8 + 4);
            bev[0]=t0.x; bev[1]=t0.y; bev[2]=t0.z; bev[3]=t0.w;
            bev[4]=t1.x; bev[5]=t1.y; bev[6]=t1.z; bev[7]=t1.w;
        }
        #pragma unroll
        for (int i = 0; i < 8; i++) {
            int row = mbase + ty * 8 + i;
            int rc = (row < NN) ? row : (NN - 1);
            float d = g_dni[rc];
            float r[8];
            upk2(acc[i][0], r[0], r[1]); upk2(acc[i][1], r[2], r[3]);
            upk2(acc[i][2], r[4], r[5]); upk2(acc[i][3], r[6], r[7]);
            float s = 0.f, q = 0.f;
            #pragma unroll
            for (int j = 0; j < 8; j++) {
                r[j] = (r[j] + biv[j]) * d;
                s += r[j]; q += r[j] * r[j];
            }
            #pragma unroll
            for (int o = 16; o > 0; o >>= 1) {
                s += __shfl_xor_sync(0xffffffffu, s, o);
                q += __shfl_xor_sync(0xffffffffu, q, o);
            }
            float mu  = s * (1.0f / 256.0f);
            float var = q * (1.0f / 256.0f) - mu * mu;
            float inv = rsqrtf(var + 1e-5f);
            float o8[8];
            #pragma unroll
            for (int j = 0; j < 8; j++) {
                float y = gav[j] * (r[j] - mu) * inv + bev[j];
                o8[j] = (y >= 0.f) ? y : alpha * y;
            }
            if (row < NN) {
                float4 v0 = { o8[0], o8[1], o8[2], o8[3] };
                float4 v1 = { o8[4], o8[5], o8[6], o8[7] };
                *(float4*)(C + (size_t)row * BN + tx * 8)     = v0;
                *(float4*)(C + (size_t)row * BN + tx * 8 + 4) = v1;
            }
        }
    } else {
        #pragma unroll
        for (int i = 0; i < 8; i++) {
            int row = mbase + ty * 8 + i;
            if (row < NN) {
                float r[8];
                upk2(acc[i][0], r[0], r[1]); upk2(acc[i][1], r[2], r[3]);
                upk2(acc[i][2], r[4], r[5]); upk2(acc[i][3], r[6], r[7]);
                float4 v0 = { r[0], r[1], r[2], r[3] };
                float4 v1 = { r[4], r[5], r[6], r[7] };
                *(float4*)(C + (size_t)row * BN + tx * 8)     = v0;
                *(float4*)(C + (size_t)row * BN + tx * 8 + 4) = v1;
            }
        }
    }
}

// ---------------- launch ----------------
extern "C" void kernel_launch(void* const* d_in, const int* in_sizes, int n_in,
                              void* d_out, int out_size) {
    const float* feat = (const float*)d_in[0];
    const float* W1 = (const float*)d_in[1];  const float* b1 = (const float*)d_in[2];
    const float* g1 = (const float*)d_in[3];  const float* be1 = (const float*)d_in[4];
    const float* a1 = (const float*)d_in[5];
    const float* W2 = (const float*)d_in[6];  const float* b2 = (const float*)d_in[7];
    const float* g2 = (const float*)d_in[8];  const float* be2 = (const float*)d_in[9];
    const float* a2 = (const float*)d_in[10];
    const float* W3 = (const float*)d_in[11]; const float* b3 = (const float*)d_in[12];
    const int* src = (const int*)d_in[13];
    const int* dst = (const int*)d_in[14];
    float* out = (float*)d_out;

    void* pA = nullptr; void* pB = nullptr;
    cudaGetSymbolAddress(&pA, g_bufA);
    cudaGetSymbolAddress(&pB, g_bufB);
    float* bufA = (float*)pA;
    float* bufB = (float*)pB;

    // degree + CSR build
    k_zero<<<(NN + 255) / 256, 256>>>();
    k_deg<<<(EE + 255) / 256, 256>>>(src, dst);
    k_norm<<<(NN + 255) / 256, 256>>>();
    k_scan<<<1, 1024>>>();
    k_fill<<<(EE + 255) / 256, 256>>>(src, dst);

    // layer 1: aggregate at D=128, then GEMM 128->256 (+bias,deg_in,LN,PReLU)
    k_agg<128, false><<<(NN + 7) / 8, 256>>>(feat, bufA, nullptr);
    k_gemm<128, 256, true><<<(NN + 127) / 128, 512>>>(bufA, W1, b1, g1, be1, a1, bufB);

    // layer 2: aggregate at D=256, GEMM 256->256 (+epilogue)
    k_agg<256, false><<<(NN + 7) / 8, 256>>>(bufB, bufA, nullptr);
    k_gemm<256, 256, true><<<(NN + 127) / 128, 512>>>(bufA, W2, b2, g2, be2, a2, bufB);

    // layer 3: GEMM first (256->128, raw), then aggregate at D=128 with (+b3)*deg_in
    k_gemm<256, 128, false><<<(NN + 255) / 256, 512>>>(bufB, W3, nullptr, nullptr,
                                                       nullptr, nullptr, bufA);
    k_agg<128, true><<<(NN + 7) / 8, 256>>>(bufA, out, b3);
}

// round 3
// speedup vs baseline: 1.4750x; 1.4750x over previous
#include <cuda_runtime.h>
#include <cuda_bf16.h>
#include <cstdint>

#define NN 100000
#define EE 1600000
#define NSB 98            // ceil(NN/1024)
typedef unsigned long long u64;
typedef unsigned int u32;

// ---------------- device scratch ----------------
__device__ float g_bufA[(size_t)NN * 256];
__device__ __nv_bfloat16 g_h1[(size_t)NN * 256];
__device__ __nv_bfloat16 g_l1[(size_t)NN * 256];
__device__ __nv_bfloat16 g_h2[(size_t)NN * 256];
__device__ __nv_bfloat16 g_l2[(size_t)NN * 256];
__device__ __nv_bfloat16 g_w1h[256 * 128], g_w1l[256 * 128];
__device__ __nv_bfloat16 g_w2h[256 * 256], g_w2l[256 * 256];
__device__ __nv_bfloat16 g_w3h[128 * 256], g_w3l[128 * 256];
__device__ float g_dno[NN], g_dni[NN];
__device__ int g_cout[NN], g_cin[NN];
__device__ int g_ptr[NN + 1], g_cur[NN], g_csrc[EE];
__device__ int g_part[128], g_poff[128];

// ---------------- helpers ----------------
__device__ __forceinline__ u32 pkbf(float a, float b) {
    __nv_bfloat16 ha = __float2bfloat16(a), hb = __float2bfloat16(b);
    unsigned short ua = *(unsigned short*)&ha, ub = *(unsigned short*)&hb;
    return ((u32)ub << 16) | (u32)ua;
}
__device__ __forceinline__ void bsplit2(float a, float b, u32& h, u32& l) {
    __nv_bfloat16 ha = __float2bfloat16(a), hb = __float2bfloat16(b);
    h = ((u32)(*(unsigned short*)&hb) << 16) | (u32)(*(unsigned short*)&ha);
    l = pkbf(a - __bfloat162float(ha), b - __bfloat162float(hb));
}
__device__ __forceinline__ void fma4(float4& a, float w, const float4 v) {
    a.x = fmaf(w, v.x, a.x); a.y = fmaf(w, v.y, a.y);
    a.z = fmaf(w, v.z, a.z); a.w = fmaf(w, v.w, a.w);
}
__device__ __forceinline__ void mma16816(float* c, const u32* a, const u32* b) {
    asm volatile(
        "mma.sync.aligned.m16n8k16.row.col.f32.bf16.bf16.f32 "
        "{%0,%1,%2,%3},{%4,%5,%6,%7},{%8,%9},{%0,%1,%2,%3};"
        : "+f"(c[0]), "+f"(c[1]), "+f"(c[2]), "+f"(c[3])
        : "r"(a[0]), "r"(a[1]), "r"(a[2]), "r"(a[3]), "r"(b[0]), "r"(b[1]));
}

// ---------------- prep ----------------
__global__ void k_zero() {
    int i = blockIdx.x * blockDim.x + threadIdx.x;
    if (i < NN) { g_cout[i] = 0; g_cin[i] = 0; }
}
__global__ void k_deg(const int* __restrict__ src, const int* __restrict__ dst) {
    int i = blockIdx.x * blockDim.x + threadIdx.x;
    if (i < EE) {
        atomicAdd(&g_cout[src[i]], 1);
        atomicAdd(&g_cin[dst[i]], 1);
    }
}
__global__ void k_norm() {
    int i = blockIdx.x * blockDim.x + threadIdx.x;
    if (i < NN) {
        int co = g_cout[i]; if (co < 1) co = 1;
        int ci = g_cin[i];  if (ci < 1) ci = 1;
        g_dno[i] = rsqrtf((float)co);
        g_dni[i] = rsqrtf((float)ci);
    }
}
__global__ void k_part() {
    int b = blockIdx.x, tid = threadIdx.x;
    int s = 0;
    for (int j = tid; j < 1024; j += 256) {
        int i = b * 1024 + j;
        s += (i < NN) ? g_cin[i] : 0;
    }
    #pragma unroll
    for (int o = 16; o; o >>= 1) s += __shfl_xor_sync(0xffffffffu, s, o);
    __shared__ int sh[8];
    if ((tid & 31) == 0) sh[tid >> 5] = s;
    __syncthreads();
    if (tid == 0) {
        int t = 0;
        #pragma unroll
        for (int j = 0; j < 8; j++) t += sh[j];
        g_part[b] = t;
    }
}
__global__ void k_pscan() {
    __shared__ int ws[4], ws2[4];
    int tid = threadIdx.x, lane = tid & 31, w = tid >> 5;
    int v = (tid < NSB) ? g_part[tid] : 0;
    int x = v;
    #pragma unroll
    for (int o = 1; o < 32; o <<= 1) {
        int t = __shfl_up_sync(0xffffffffu, x, o);
        if (lane >= o) x += t;
    }
    if (lane == 31) ws[w] = x;
    __syncthreads();
    if (tid == 0) {
        int run = 0;
        #pragma unroll
        for (int j = 0; j < 4; j++) { ws2[j] = run; run += ws[j]; }
    }
    __syncthreads();
    if (tid < NSB) g_poff[tid] = ws2[w] + x - v;
}
__global__ void k_scat() {
    __shared__ int ws[32];
    int b = blockIdx.x, tid = threadIdx.x;
    int lane = tid & 31, w = tid >> 5;
    int i = b * 1024 + tid;
    int v = (i < NN) ? g_cin[i] : 0;
    int x = v;
    #pragma unroll
    for (int o = 1; o < 32; o <<= 1) {
        int t = __shfl_up_sync(0xffffffffu, x, o);
        if (lane >= o) x += t;
    }
    if (lane == 31) ws[w] = x;
    __syncthreads();
    if (w == 0) {
        int s = ws[lane];
        #pragma unroll
        for (int o = 1; o < 32; o <<= 1) {
            int t = __shfl_up_sync(0xffffffffu, s, o);
            if (lane >= o) s += t;
        }
        ws[lane] = s;
    }
    __syncthreads();
    int pre = (w > 0) ? ws[w - 1] : 0;
    int exc = g_poff[b] + pre + x - v;
    if (i < NN) { g_ptr[i] = exc; g_cur[i] = exc; }
    if (b == 0 && tid == 0) g_ptr[NN] = EE;
}
__global__ void k_fill(const int* __restrict__ src, const int* __restrict__ dst) {
    int i = blockIdx.x * blockDim.x + threadIdx.x;
    if (i < EE) {
        int d = dst[i];
        int p = atomicAdd(&g_cur[d], 1);
        g_csrc[p] = src[i];
    }
}
// transpose + bf16-split weights: W[K,Nout] -> H/L[Nout,K]
__global__ void k_wsplit(const float* __restrict__ W, __nv_bfloat16* __restrict__ H,
                         __nv_bfloat16* __restrict__ L, int Kd, int Nout) {
    int i = blockIdx.x * blockDim.x + threadIdx.x;
    if (i < Kd * Nout) {
        int n = i / Kd, k = i % Kd;
        float v = W[(size_t)k * Nout + n];
        __nv_bfloat16 h = __float2bfloat16(v);
        float l = v - __bfloat162float(h);
        H[i] = h;
        L[i] = __float2bfloat16(l);
    }
}

// ---------------- aggregation (warp-per-node, CSR) ----------------
// MODE 1: write bf16 hi/lo split; MODE 2: (acc+b3)*dni -> f32 out
template<int D, int MODE>
__global__ void k_agg(const float* __restrict__ in,
                      __nv_bfloat16* __restrict__ oh, __nv_bfloat16* __restrict__ ol,
                      float* __restrict__ of, const float* __restrict__ b3) {
    const int w = (blockIdx.x << 3) + (threadIdx.x >> 5);
    const int lane = threadIdx.x & 31;
    if (w >= NN) return;
    const int beg = g_ptr[w], end = g_ptr[w + 1];
    float4 a0 = make_float4(0.f, 0.f, 0.f, 0.f);
    float4 a1 = make_float4(0.f, 0.f, 0.f, 0.f);
    const float4* __restrict__ inp = (const float4*)in;

    int e = beg;
    for (; e + 2 <= end; e += 2) {
        int s0 = g_csrc[e], s1 = g_csrc[e + 1];
        float w0 = g_dno[s0], w1 = g_dno[s1];
        const float4* r0 = inp + (size_t)s0 * (D / 4);
        const float4* r1 = inp + (size_t)s1 * (D / 4);
        float4 v0 = r0[lane], v1 = r1[lane];
        fma4(a0, w0, v0); fma4(a0, w1, v1);
        if (D == 256) {
            float4 u0 = r0[lane + 32], u1 = r1[lane + 32];
            fma4(a1, w0, u0); fma4(a1, w1, u1);
        }
    }
    if (e < end) {
        int s0 = g_csrc[e];
        float w0 = g_dno[s0];
        const float4* r0 = inp + (size_t)s0 * (D / 4);
        fma4(a0, w0, r0[lane]);
        if (D == 256) fma4(a1, w0, r0[lane + 32]);
    }
    if (MODE == 1) {
        uint2 hv, lv;
        bsplit2(a0.x, a0.y, hv.x, lv.x);
        bsplit2(a0.z, a0.w, hv.y, lv.y);
        ((uint2*)(oh + (size_t)w * D))[lane] = hv;
        ((uint2*)(ol + (size_t)w * D))[lane] = lv;
        if (D == 256) {
            bsplit2(a1.x, a1.y, hv.x, lv.x);
            bsplit2(a1.z, a1.w, hv.y, lv.y);
            ((uint2*)(oh + (size_t)w * D))[lane + 32] = hv;
            ((uint2*)(ol + (size_t)w * D))[lane + 32] = lv;
        }
    } else {
        float4 bb = ((const float4*)b3)[lane];
        float d = g_dni[w];
        a0.x = (a0.x + bb.x) * d; a0.y = (a0.y + bb.y) * d;
        a0.z = (a0.z + bb.z) * d; a0.w = (a0.w + bb.w) * d;
        ((float4*)(of + (size_t)w * D))[lane] = a0;
    }
}

// ---------------- bf16-split GEMM via mma.sync (HMMA) ----------------
// C[BM/blk, N] = A[.,K] @ Wt[N,K]^T  using Ah*Bh + Ah*Bl + Al*Bh
// EPI 0: raw f32 ; 1: bias,deg,LN,PReLU -> f32 ; 2: same -> bf16 split
template<int K, int BM, int N, int EPI>
__global__ void __launch_bounds__(256, 1)
k_mmagemm(const __nv_bfloat16* __restrict__ Ahi, const __nv_bfloat16* __restrict__ Alo,
          const __nv_bfloat16* __restrict__ Bhi, const __nv_bfloat16* __restrict__ Blo,
          const float* __restrict__ bias, const float* __restrict__ gam,
          const float* __restrict__ bet, const float* __restrict__ alp,
          float* __restrict__ Cf, __nv_bfloat16* __restrict__ Chi,
          __nv_bfloat16* __restrict__ Clo) {
    extern __shared__ char smem[];
    constexpr int MW = BM / 64;         // warp-rows
    constexpr int NW = N / 64;          // warp-cols
    static_assert(MW * NW == 8, "8 warps");
    constexpr int SA = 80;              // smem row stride (bytes) for 32-bf16 rows
    char* sAh = smem;
    char* sAl = smem + (size_t)BM * SA;
    char* sBh = smem + (size_t)2 * BM * SA;
    char* sBl = smem + (size_t)2 * BM * SA + (size_t)N * SA;
    constexpr int POFF = 2 * SA * (BM + N);
    float* pbias = (float*)(smem + POFF);
    float* pgam  = pbias + N;
    float* pbet  = pgam + N;

    const int tid = threadIdx.x;
    const int wid = tid >> 5, lane = tid & 31;
    const int g = lane >> 2, ti = lane & 3;
    const int mw = wid / NW, nw = wid % NW;
    const int mbase = blockIdx.x * BM;

    if (EPI >= 1) {
        for (int i = tid; i < N; i += 256) {
            pbias[i] = bias[i]; pgam[i] = gam[i]; pbet[i] = bet[i];
        }
    }

    float acc[4][8][4];
    #pragma unroll
    for (int t = 0; t < 4; t++)
        #pragma unroll
        for (int j = 0; j < 8; j++)
            #pragma unroll
            for (int q = 0; q < 4; q++) acc[t][j][q] = 0.f;

    for (int kb = 0; kb < K; kb += 32) {
        // load A tile (BM x 32 bf16, hi+lo)
        #pragma unroll
        for (int i = tid; i < BM * 8; i += 256) {
            int r = i >> 3, q = i & 7;
            int rg = mbase + r; if (rg > NN - 1) rg = NN - 1;
            size_t go = (size_t)rg * K + kb;
            *(uint2*)(sAh + r * SA + q * 8) = ((const uint2*)(Ahi + go))[q];
            *(uint2*)(sAl + r * SA + q * 8) = ((const uint2*)(Alo + go))[q];
        }
        // load B tile (N x 32 bf16, hi+lo)
        #pragma unroll
        for (int i = tid; i < N * 8; i += 256) {
            int r = i >> 3, q = i & 7;
            size_t go = (size_t)r * K + kb;
            *(uint2*)(sBh + r * SA + q * 8) = ((const uint2*)(Bhi + go))[q];
            *(uint2*)(sBl + r * SA + q * 8) = ((const uint2*)(Blo + go))[q];
        }
        __syncthreads();
        #pragma unroll
        for (int kt = 0; kt < 2; kt++) {
            const int kof = kt * 32 + ti * 4;
            u32 ah[4][4], al[4][4];
            #pragma unroll
            for (int t = 0; t < 4; t++) {
                const char* p = sAh + (mw * 64 + t * 16 + g) * SA + kof;
                ah[t][0] = *(const u32*)p;
                ah[t][1] = *(const u32*)(p + 8 * SA);
                ah[t][2] = *(const u32*)(p + 16);
                ah[t][3] = *(const u32*)(p + 8 * SA + 16);
                const char* pl = sAl + (mw * 64 + t * 16 + g) * SA + kof;
                al[t][0] = *(const u32*)pl;
                al[t][1] = *(const u32*)(pl + 8 * SA);
                al[t][2] = *(const u32*)(pl + 16);
                al[t][3] = *(const u32*)(pl + 8 * SA + 16);
            }
            #pragma unroll
            for (int j = 0; j < 8; j++) {
                const char* pb = sBh + (nw * 64 + j * 8 + g) * SA + kof;
                u32 bh[2] = { *(const u32*)pb, *(const u32*)(pb + 16) };
                const char* pbl = sBl + (nw * 64 + j * 8 + g) * SA + kof;
                u32 bl[2] = { *(const u32*)pbl, *(const u32*)(pbl + 16) };
                #pragma unroll
                for (int t = 0; t < 4; t++) {
                    mma16816(acc[t][j], ah[t], bh);
                    mma16816(acc[t][j], ah[t], bl);
                    mma16816(acc[t][j], al[t], bh);
                }
            }
        }
        __syncthreads();
    }

    if (EPI == 0) {
        #pragma unroll
        for (int t = 0; t < 4; t++) {
            int rl = mbase + mw * 64 + t * 16 + g;
            int rh = rl + 8;
            #pragma unroll
            for (int j = 0; j < 8; j++) {
                int c = nw * 64 + j * 8 + ti * 2;
                if (rl < NN)
                    *(float2*)(Cf + (size_t)rl * N + c) = make_float2(acc[t][j][0], acc[t][j][1]);
                if (rh < NN)
                    *(float2*)(Cf + (size_t)rh * N + c) = make_float2(acc[t][j][2], acc[t][j][3]);
            }
        }
        return;
    }

    // fused epilogue: v=(acc+bias)*dni; LN; PReLU
    float* red = (float*)smem;  // [BM][NW][2], reuses tile smem
    float mul[4], invl[4], muh[4], invh[4];
    #pragma unroll
    for (int t = 0; t < 4; t++) {
        int rloc = mw * 64 + t * 16 + g;
        int rl = mbase + rloc, rh = rl + 8;
        float dl = g_dni[(rl < NN) ? rl : (NN - 1)];
        float dh = g_dni[(rh < NN) ? rh : (NN - 1)];
        float s0 = 0.f, q0 = 0.f, s1 = 0.f, q1 = 0.f;
        #pragma unroll
        for (int j = 0; j < 8; j++) {
            int c = nw * 64 + j * 8 + ti * 2;
            float b0 = pbias[c], b1 = pbias[c + 1];
            float v0 = (acc[t][j][0] + b0) * dl;
            float v1 = (acc[t][j][1] + b1) * dl;
            float v2 = (acc[t][j][2] + b0) * dh;
            float v3 = (acc[t][j][3] + b1) * dh;
            acc[t][j][0] = v0; acc[t][j][1] = v1;
            acc[t][j][2] = v2; acc[t][j][3] = v3;
            s0 += v0 + v1; q0 += v0 * v0 + v1 * v1;
            s1 += v2 + v3; q1 += v2 * v2 + v3 * v3;
        }
        #pragma unroll
        for (int o = 1; o <= 2; o <<= 1) {
            s0 += __shfl_xor_sync(0xffffffffu, s0, o);
            q0 += __shfl_xor_sync(0xffffffffu, q0, o);
            s1 += __shfl_xor_sync(0xffffffffu, s1, o);
            q1 += __shfl_xor_sync(0xffffffffu, q1, o);
        }
        if (ti == 0) {
            red[(rloc * NW + nw) * 2 + 0] = s0;
            red[(rloc * NW + nw) * 2 + 1] = q0;
            red[((rloc + 8) * NW + nw) * 2 + 0] = s1;
            red[((rloc + 8) * NW + nw) * 2 + 1] = q1;
        }
    }
    __syncthreads();
    #pragma unroll
    for (int t = 0; t < 4; t++) {
        int rloc = mw * 64 + t * 16 + g;
        float s0 = 0.f, q0 = 0.f, s1 = 0.f, q1 = 0.f;
        #pragma unroll
        for (int k = 0; k < NW; k++) {
            s0 += red[(rloc * NW + k) * 2 + 0];
            q0 += red[(rloc * NW + k) * 2 + 1];
            s1 += red[((rloc + 8) * NW + k) * 2 + 0];
            q1 += red[((rloc + 8) * NW + k) * 2 + 1];
        }
        float m0 = s0 * (1.0f / N), m1 = s1 * (1.0f / N);
        mul[t] = m0; muh[t] = m1;
        invl[t] = rsqrtf(q0 * (1.0f / N) - m0 * m0 + 1e-5f);
        invh[t] = rsqrtf(q1 * (1.0f / N) - m1 * m1 + 1e-5f);
    }
    const float alpha = __ldg(alp);
    #pragma unroll
    for (int t = 0; t < 4; t++) {
        int rl = mbase + mw * 64 + t * 16 + g;
        int rh = rl + 8;
        #pragma unroll
        for (int j = 0; j < 8; j++) {
            int c = nw * 64 + j * 8 + ti * 2;
            float g0 = pgam[c], g1 = pgam[c + 1];
            float e0 = pbet[c], e1 = pbet[c + 1];
            float y0 = g0 * (acc[t][j][0] - mul[t]) * invl[t] + e0;
            float y1 = g1 * (acc[t][j][1] - mul[t]) * invl[t] + e1;
            float y2 = g0 * (acc[t][j][2] - muh[t]) * invh[t] + e0;
            float y3 = g1 * (acc[t][j][3] - muh[t]) * invh[t] + e1;
            y0 = (y0 >= 0.f) ? y0 : alpha * y0;
            y1 = (y1 >= 0.f) ? y1 : alpha * y1;
            y2 = (y2 >= 0.f) ? y2 : alpha * y2;
            y3 = (y3 >= 0.f) ? y3 : alpha * y3;
            if (EPI == 1) {
                if (rl < NN) *(float2*)(Cf + (size_t)rl * N + c) = make_float2(y0, y1);
                if (rh < NN) *(float2*)(Cf + (size_t)rh * N + c) = make_float2(y2, y3);
            } else {
                u32 h01, l01, h23, l23;
                bsplit2(y0, y1, h01, l01);
                bsplit2(y2, y3, h23, l23);
                if (rl < NN) {
                    *(u32*)(Chi + (size_t)rl * N + c) = h01;
                    *(u32*)(Clo + (size_t)rl * N + c) = l01;
                }
                if (rh < NN) {
                    *(u32*)(Chi + (size_t)rh * N + c) = h23;
                    *(u32*)(Clo + (size_t)rh * N + c) = l23;
                }
            }
        }
    }
}

// ---------------- launch ----------------
extern "C" void kernel_launch(void* const* d_in, const int* in_sizes, int n_in,
                              void* d_out, int out_size) {
    const float* feat = (const float*)d_in[0];
    const float* W1 = (const float*)d_in[1];  const float* b1 = (const float*)d_in[2];
    const float* g1 = (const float*)d_in[3];  const float* be1 = (const float*)d_in[4];
    const float* a1 = (const float*)d_in[5];
    const float* W2 = (const float*)d_in[6];  const float* b2 = (const float*)d_in[7];
    const float* g2 = (const float*)d_in[8];  const float* be2 = (const float*)d_in[9];
    const float* a2 = (const float*)d_in[10];
    const float* W3 = (const float*)d_in[11]; const float* b3 = (const float*)d_in[12];
    const int* src = (const int*)d_in[13];
    const int* dst = (const int*)d_in[14];
    float* out = (float*)d_out;

    void* p;
    cudaGetSymbolAddress(&p, g_bufA);  float* bufA = (float*)p;
    cudaGetSymbolAddress(&p, g_h1);    __nv_bfloat16* h1 = (__nv_bfloat16*)p;
    cudaGetSymbolAddress(&p, g_l1);    __nv_bfloat16* l1 = (__nv_bfloat16*)p;
    cudaGetSymbolAddress(&p, g_h2);    __nv_bfloat16* h2 = (__nv_bfloat16*)p;
    cudaGetSymbolAddress(&p, g_l2);    __nv_bfloat16* l2 = (__nv_bfloat16*)p;
    cudaGetSymbolAddress(&p, g_w1h);   __nv_bfloat16* w1h = (__nv_bfloat16*)p;
    cudaGetSymbolAddress(&p, g_w1l);   __nv_bfloat16* w1l = (__nv_bfloat16*)p;
    cudaGetSymbolAddress(&p, g_w2h);   __nv_bfloat16* w2h = (__nv_bfloat16*)p;
    cudaGetSymbolAddress(&p, g_w2l);   __nv_bfloat16* w2l = (__nv_bfloat16*)p;
    cudaGetSymbolAddress(&p, g_w3h);   __nv_bfloat16* w3h = (__nv_bfloat16*)p;
    cudaGetSymbolAddress(&p, g_w3l);   __nv_bfloat16* w3l = (__nv_bfloat16*)p;

    // smem: tiles 2*80*(BM+N) = 61440 for both shapes, + 3*N floats params
    constexpr int SM1 = 61440 + 3 * 256 * 4;
    constexpr int SM3 = 61440 + 3 * 128 * 4;
    cudaFuncSetAttribute(k_mmagemm<128, 128, 256, 1>, cudaFuncAttributeMaxDynamicSharedMemorySize, SM1);
    cudaFuncSetAttribute(k_mmagemm<256, 128, 256, 2>, cudaFuncAttributeMaxDynamicSharedMemorySize, SM1);
    cudaFuncSetAttribute(k_mmagemm<256, 256, 128, 0>, cudaFuncAttributeMaxDynamicSharedMemorySize, SM3);

    // degree + CSR
    k_zero<<<(NN + 255) / 256, 256>>>();
    k_deg<<<(EE + 255) / 256, 256>>>(src, dst);
    k_norm<<<(NN + 255) / 256, 256>>>();
    k_part<<<NSB, 256>>>();
    k_pscan<<<1, 128>>>();
    k_scat<<<NSB, 1024>>>();
    k_fill<<<(EE + 255) / 256, 256>>>(src, dst);

    // weight transpose + split
    k_wsplit<<<(128 * 256 + 255) / 256, 256>>>(W1, w1h, w1l, 128, 256);
    k_wsplit<<<(256 * 256 + 255) / 256, 256>>>(W2, w2h, w2l, 256, 256);
    k_wsplit<<<(256 * 128 + 255) / 256, 256>>>(W3, w3h, w3l, 256, 128);

    // layer 1: agg(feat) -> split ; GEMM 128->256 + LN epilogue -> f32
    k_agg<128, 1><<<(NN + 7) / 8, 256>>>(feat, h1, l1, nullptr, nullptr);
    k_mmagemm<128, 128, 256, 1><<<(NN + 127) / 128, 256, SM1>>>(
        h1, l1, w1h, w1l, b1, g1, be1, a1, bufA, nullptr, nullptr);

    // layer 2: agg -> split ; GEMM 256->256 + LN epilogue -> bf16 split
    k_agg<256, 1><<<(NN + 7) / 8, 256>>>(bufA, h1, l1, nullptr, nullptr);
    k_mmagemm<256, 128, 256, 2><<<(NN + 127) / 128, 256, SM1>>>(
        h1, l1, w2h, w2l, b2, g2, be2, a2, nullptr, h2, l2);

    // layer 3: GEMM 256->128 raw -> f32 ; agg final with (x+b3)*deg_in
    k_mmagemm<256, 256, 128, 0><<<(NN + 255) / 256, 256, SM3>>>(
        h2, l2, w3h, w3l, nullptr, nullptr, nullptr, nullptr, bufA, nullptr, nullptr);
    k_agg<128, 2><<<(NN + 7) / 8, 256>>>(bufA, nullptr, nullptr, out, b3);
}

// round 4
// speedup vs baseline: 1.6052x; 1.0883x over previous
#include <cuda_runtime.h>
#include <cuda_bf16.h>
#include <cstdint>

#define NN 100000
#define EE 1600000
#define NSB 98            // ceil(NN/1024)
typedef unsigned long long u64;
typedef unsigned int u32;

// ---------------- device scratch ----------------
__device__ float g_bufA[(size_t)NN * 256];
__device__ __nv_bfloat16 g_h1[(size_t)NN * 256];
__device__ __nv_bfloat16 g_l1[(size_t)NN * 256];
__device__ __nv_bfloat16 g_h2[(size_t)NN * 256];
__device__ __nv_bfloat16 g_l2[(size_t)NN * 256];
__device__ __nv_bfloat16 g_w1h[256 * 128], g_w1l[256 * 128];
__device__ __nv_bfloat16 g_w2h[256 * 256], g_w2l[256 * 256];
__device__ __nv_bfloat16 g_w3h[128 * 256], g_w3l[128 * 256];
__device__ float g_dno[NN], g_dni[NN];
__device__ int g_cout[NN], g_cin[NN];
__device__ int g_ptr[NN + 1], g_cur[NN], g_csrc[EE];
__device__ int g_part[128], g_poff[128];

// ---------------- helpers ----------------
__device__ __forceinline__ u32 pkbf(float a, float b) {
    __nv_bfloat16 ha = __float2bfloat16(a), hb = __float2bfloat16(b);
    unsigned short ua = *(unsigned short*)&ha, ub = *(unsigned short*)&hb;
    return ((u32)ub << 16) | (u32)ua;
}
__device__ __forceinline__ void bsplit2(float a, float b, u32& h, u32& l) {
    __nv_bfloat16 ha = __float2bfloat16(a), hb = __float2bfloat16(b);
    h = ((u32)(*(unsigned short*)&hb) << 16) | (u32)(*(unsigned short*)&ha);
    l = pkbf(a - __bfloat162float(ha), b - __bfloat162float(hb));
}
__device__ __forceinline__ void fma4(float4& a, float w, const float4 v) {
    a.x = fmaf(w, v.x, a.x); a.y = fmaf(w, v.y, a.y);
    a.z = fmaf(w, v.z, a.z); a.w = fmaf(w, v.w, a.w);
}
__device__ __forceinline__ void mma16816(float* c, const u32* a, const u32* b) {
    asm volatile(
        "mma.sync.aligned.m16n8k16.row.col.f32.bf16.bf16.f32 "
        "{%0,%1,%2,%3},{%4,%5,%6,%7},{%8,%9},{%0,%1,%2,%3};"
        : "+f"(c[0]), "+f"(c[1]), "+f"(c[2]), "+f"(c[3])
        : "r"(a[0]), "r"(a[1]), "r"(a[2]), "r"(a[3]), "r"(b[0]), "r"(b[1]));
}
__device__ __forceinline__ void cpa16(void* s, const void* g) {
    u32 sa = (u32)__cvta_generic_to_shared(s);
    asm volatile("cp.async.cg.shared.global [%0], [%1], 16;" :: "r"(sa), "l"(g));
}

// ---------------- prep ----------------
__global__ void k_zero() {
    int i = blockIdx.x * blockDim.x + threadIdx.x;
    if (i < NN) { g_cout[i] = 0; g_cin[i] = 0; }
}
__global__ void k_deg(const int* __restrict__ src, const int* __restrict__ dst) {
    int i = blockIdx.x * blockDim.x + threadIdx.x;
    if (i < EE) {
        atomicAdd(&g_cout[src[i]], 1);
        atomicAdd(&g_cin[dst[i]], 1);
    }
}
__global__ void k_norm() {
    int i = blockIdx.x * blockDim.x + threadIdx.x;
    if (i < NN) {
        int co = g_cout[i]; if (co < 1) co = 1;
        int ci = g_cin[i];  if (ci < 1) ci = 1;
        g_dno[i] = rsqrtf((float)co);
        g_dni[i] = rsqrtf((float)ci);
    }
}
__global__ void k_part() {
    int b = blockIdx.x, tid = threadIdx.x;
    int s = 0;
    for (int j = tid; j < 1024; j += 256) {
        int i = b * 1024 + j;
        s += (i < NN) ? g_cin[i] : 0;
    }
    #pragma unroll
    for (int o = 16; o; o >>= 1) s += __shfl_xor_sync(0xffffffffu, s, o);
    __shared__ int sh[8];
    if ((tid & 31) == 0) sh[tid >> 5] = s;
    __syncthreads();
    if (tid == 0) {
        int t = 0;
        #pragma unroll
        for (int j = 0; j < 8; j++) t += sh[j];
        g_part[b] = t;
    }
}
__global__ void k_pscan() {
    __shared__ int ws[4], ws2[4];
    int tid = threadIdx.x, lane = tid & 31, w = tid >> 5;
    int v = (tid < NSB) ? g_part[tid] : 0;
    int x = v;
    #pragma unroll
    for (int o = 1; o < 32; o <<= 1) {
        int t = __shfl_up_sync(0xffffffffu, x, o);
        if (lane >= o) x += t;
    }
    if (lane == 31) ws[w] = x;
    __syncthreads();
    if (tid == 0) {
        int run = 0;
        #pragma unroll
        for (int j = 0; j < 4; j++) { ws2[j] = run; run += ws[j]; }
    }
    __syncthreads();
    if (tid < NSB) g_poff[tid] = ws2[w] + x - v;
}
__global__ void k_scat() {
    __shared__ int ws[32];
    int b = blockIdx.x, tid = threadIdx.x;
    int lane = tid & 31, w = tid >> 5;
    int i = b * 1024 + tid;
    int v = (i < NN) ? g_cin[i] : 0;
    int x = v;
    #pragma unroll
    for (int o = 1; o < 32; o <<= 1) {
        int t = __shfl_up_sync(0xffffffffu, x, o);
        if (lane >= o) x += t;
    }
    if (lane == 31) ws[w] = x;
    __syncthreads();
    if (w == 0) {
        int s = ws[lane];
        #pragma unroll
        for (int o = 1; o < 32; o <<= 1) {
            int t = __shfl_up_sync(0xffffffffu, s, o);
            if (lane >= o) s += t;
        }
        ws[lane] = s;
    }
    __syncthreads();
    int pre = (w > 0) ? ws[w - 1] : 0;
    int exc = g_poff[b] + pre + x - v;
    if (i < NN) { g_ptr[i] = exc; g_cur[i] = exc; }
    if (b == 0 && tid == 0) g_ptr[NN] = EE;
}
__global__ void k_fill(const int* __restrict__ src, const int* __restrict__ dst) {
    int i = blockIdx.x * blockDim.x + threadIdx.x;
    if (i < EE) {
        int d = dst[i];
        int p = atomicAdd(&g_cur[d], 1);
        g_csrc[p] = src[i];
    }
}
// transpose + bf16-split weights: W[K,Nout] -> H/L[Nout,K]
__global__ void k_wsplit(const float* __restrict__ W, __nv_bfloat16* __restrict__ H,
                         __nv_bfloat16* __restrict__ L, int Kd, int Nout) {
    int i = blockIdx.x * blockDim.x + threadIdx.x;
    if (i < Kd * Nout) {
        int n = i / Kd, k = i % Kd;
        float v = W[(size_t)k * Nout + n];
        __nv_bfloat16 h = __float2bfloat16(v);
        float l = v - __bfloat162float(h);
        H[i] = h;
        L[i] = __float2bfloat16(l);
    }
}

// ---------------- aggregation (warp-per-node, CSR) ----------------
// MODE 1: write bf16 hi/lo split; MODE 2: (acc+b3)*dni -> f32 out
template<int D, int MODE>
__global__ void k_agg(const float* __restrict__ in,
                      __nv_bfloat16* __restrict__ oh, __nv_bfloat16* __restrict__ ol,
                      float* __restrict__ of, const float* __restrict__ b3) {
    const int w = (blockIdx.x << 3) + (threadIdx.x >> 5);
    const int lane = threadIdx.x & 31;
    if (w >= NN) return;
    const int beg = g_ptr[w], end = g_ptr[w + 1];
    float4 a0 = make_float4(0.f, 0.f, 0.f, 0.f);
    float4 a1 = make_float4(0.f, 0.f, 0.f, 0.f);
    const float4* __restrict__ inp = (const float4*)in;

    int e = beg;
    for (; e + 4 <= end; e += 4) {
        int s0 = g_csrc[e], s1 = g_csrc[e + 1];
        int s2 = g_csrc[e + 2], s3 = g_csrc[e + 3];
        float w0 = g_dno[s0], w1 = g_dno[s1];
        float w2 = g_dno[s2], w3 = g_dno[s3];
        const float4* r0 = inp + (size_t)s0 * (D / 4);
        const float4* r1 = inp + (size_t)s1 * (D / 4);
        const float4* r2 = inp + (size_t)s2 * (D / 4);
        const float4* r3 = inp + (size_t)s3 * (D / 4);
        float4 v0 = r0[lane], v1 = r1[lane], v2 = r2[lane], v3 = r3[lane];
        fma4(a0, w0, v0); fma4(a0, w1, v1); fma4(a0, w2, v2); fma4(a0, w3, v3);
        if (D == 256) {
            float4 u0 = r0[lane + 32], u1 = r1[lane + 32];
            float4 u2 = r2[lane + 32], u3 = r3[lane + 32];
            fma4(a1, w0, u0); fma4(a1, w1, u1); fma4(a1, w2, u2); fma4(a1, w3, u3);
        }
    }
    for (; e < end; e++) {
        int s0 = g_csrc[e];
        float w0 = g_dno[s0];
        const float4* r0 = inp + (size_t)s0 * (D / 4);
        fma4(a0, w0, r0[lane]);
        if (D == 256) fma4(a1, w0, r0[lane + 32]);
    }
    if (MODE == 1) {
        uint2 hv, lv;
        bsplit2(a0.x, a0.y, hv.x, lv.x);
        bsplit2(a0.z, a0.w, hv.y, lv.y);
        ((uint2*)(oh + (size_t)w * D))[lane] = hv;
        ((uint2*)(ol + (size_t)w * D))[lane] = lv;
        if (D == 256) {
            bsplit2(a1.x, a1.y, hv.x, lv.x);
            bsplit2(a1.z, a1.w, hv.y, lv.y);
            ((uint2*)(oh + (size_t)w * D))[lane + 32] = hv;
            ((uint2*)(ol + (size_t)w * D))[lane + 32] = lv;
        }
    } else {
        float4 bb = ((const float4*)b3)[lane];
        float d = g_dni[w];
        a0.x = (a0.x + bb.x) * d; a0.y = (a0.y + bb.y) * d;
        a0.z = (a0.z + bb.z) * d; a0.w = (a0.w + bb.w) * d;
        ((float4*)(of + (size_t)w * D))[lane] = a0;
    }
}

// ---------------- bf16-split GEMM via mma.sync (HMMA), cp.async 2-stage ----------------
// C[BM/blk, N] = A[.,K] @ Wt[N,K]^T  using Ah*Bh + Ah*Bl + Al*Bh
// EPI 0: raw f32 ; 1: bias,deg,LN,PReLU -> f32 ; 2: same -> bf16 split
template<int K, int BM, int N, int EPI>
__global__ void __launch_bounds__(256, 1)
k_mmagemm(const __nv_bfloat16* __restrict__ Ahi, const __nv_bfloat16* __restrict__ Alo,
          const __nv_bfloat16* __restrict__ Bhi, const __nv_bfloat16* __restrict__ Blo,
          const float* __restrict__ bias, const float* __restrict__ gam,
          const float* __restrict__ bet, const float* __restrict__ alp,
          float* __restrict__ Cf, __nv_bfloat16* __restrict__ Chi,
          __nv_bfloat16* __restrict__ Clo) {
    extern __shared__ char smem[];
    constexpr int MW = BM / 64;         // warp-rows
    constexpr int NW = N / 64;          // warp-cols
    static_assert(MW * NW == 8, "8 warps");
    constexpr int SA = 80;              // smem row stride (bytes) for 32-bf16 rows
    constexpr int STG = SA * (BM + N) * 2;    // one stage: Ah,Al,Bh,Bl
    constexpr int OAH = 0;
    constexpr int OAL = BM * SA;
    constexpr int OBH = 2 * BM * SA;
    constexpr int OBL = 2 * BM * SA + N * SA;
    constexpr int POFF = 2 * STG;
    float* pbias = (float*)(smem + POFF);
    float* pgam  = pbias + N;
    float* pbet  = pgam + N;

    const int tid = threadIdx.x;
    const int wid = tid >> 5, lane = tid & 31;
    const int g = lane >> 2, ti = lane & 3;
    const int mw = wid / NW, nw = wid % NW;
    const int mbase = blockIdx.x * BM;

    if (EPI >= 1) {
        for (int i = tid; i < N; i += 256) {
            pbias[i] = bias[i]; pgam[i] = gam[i]; pbet[i] = bet[i];
        }
    }

    float acc[4][8][4];
    #pragma unroll
    for (int t = 0; t < 4; t++)
        #pragma unroll
        for (int j = 0; j < 8; j++)
            #pragma unroll
            for (int q = 0; q < 4; q++) acc[t][j][q] = 0.f;

    auto issue_stage = [&](int it, int buf) {
        const int kb = it * 32;
        char* base = smem + buf * STG;
        #pragma unroll
        for (int i = tid; i < BM * 4; i += 256) {
            int r = i >> 2, q = i & 3;
            int rg = mbase + r; if (rg > NN - 1) rg = NN - 1;
            size_t go = (size_t)rg * K + kb + q * 8;
            cpa16(base + OAH + r * SA + q * 16, Ahi + go);
            cpa16(base + OAL + r * SA + q * 16, Alo + go);
        }
        #pragma unroll
        for (int i = tid; i < N * 4; i += 256) {
            int r = i >> 2, q = i & 3;
            size_t go = (size_t)r * K + kb + q * 8;
            cpa16(base + OBH + r * SA + q * 16, Bhi + go);
            cpa16(base + OBL + r * SA + q * 16, Blo + go);
        }
        asm volatile("cp.async.commit_group;" ::: "memory");
    };

    constexpr int NIT = K / 32;
    issue_stage(0, 0);
    for (int it = 0; it < NIT; it++) {
        const int buf = it & 1;
        if (it + 1 < NIT) {
            issue_stage(it + 1, buf ^ 1);
            asm volatile("cp.async.wait_group 1;" ::: "memory");
        } else {
            asm volatile("cp.async.wait_group 0;" ::: "memory");
        }
        __syncthreads();
        const char* sAh = smem + buf * STG + OAH;
        const char* sAl = smem + buf * STG + OAL;
        const char* sBh = smem + buf * STG + OBH;
        const char* sBl = smem + buf * STG + OBL;
        #pragma unroll
        for (int kt = 0; kt < 2; kt++) {
            const int kof = kt * 32 + ti * 4;
            u32 ah[4][4], al[4][4];
            #pragma unroll
            for (int t = 0; t < 4; t++) {
                const char* p = sAh + (mw * 64 + t * 16 + g) * SA + kof;
                ah[t][0] = *(const u32*)p;
                ah[t][1] = *(const u32*)(p + 8 * SA);
                ah[t][2] = *(const u32*)(p + 16);
                ah[t][3] = *(const u32*)(p + 8 * SA + 16);
                const char* pl = sAl + (mw * 64 + t * 16 + g) * SA + kof;
                al[t][0] = *(const u32*)pl;
                al[t][1] = *(const u32*)(pl + 8 * SA);
                al[t][2] = *(const u32*)(pl + 16);
                al[t][3] = *(const u32*)(pl + 8 * SA + 16);
            }
            #pragma unroll
            for (int j = 0; j < 8; j++) {
                const char* pb = sBh + (nw * 64 + j * 8 + g) * SA + kof;
                u32 bh[2] = { *(const u32*)pb, *(const u32*)(pb + 16) };
                const char* pbl = sBl + (nw * 64 + j * 8 + g) * SA + kof;
                u32 bl[2] = { *(const u32*)pbl, *(const u32*)(pbl + 16) };
                #pragma unroll
                for (int t = 0; t < 4; t++) {
                    mma16816(acc[t][j], ah[t], bh);
                    mma16816(acc[t][j], ah[t], bl);
                    mma16816(acc[t][j], al[t], bh);
                }
            }
        }
        __syncthreads();
    }

    if (EPI == 0) {
        #pragma unroll
        for (int t = 0; t < 4; t++) {
            int rl = mbase + mw * 64 + t * 16 + g;
            int rh = rl + 8;
            #pragma unroll
            for (int j = 0; j < 8; j++) {
                int c = nw * 64 + j * 8 + ti * 2;
                if (rl < NN)
                    *(float2*)(Cf + (size_t)rl * N + c) = make_float2(acc[t][j][0], acc[t][j][1]);
                if (rh < NN)
                    *(float2*)(Cf + (size_t)rh * N + c) = make_float2(acc[t][j][2], acc[t][j][3]);
            }
        }
        return;
    }

    // fused epilogue: v=(acc+bias)*dni; LN; PReLU
    float* red = (float*)smem;  // [BM][NW][2], reuses tile smem
    float mul[4], invl[4], muh[4], invh[4];
    #pragma unroll
    for (int t = 0; t < 4; t++) {
        int rloc = mw * 64 + t * 16 + g;
        int rl = mbase + rloc, rh = rl + 8;
        float dl = g_dni[(rl < NN) ? rl : (NN - 1)];
        float dh = g_dni[(rh < NN) ? rh : (NN - 1)];
        float s0 = 0.f, q0 = 0.f, s1 = 0.f, q1 = 0.f;
        #pragma unroll
        for (int j = 0; j < 8; j++) {
            int c = nw * 64 + j * 8 + ti * 2;
            float b0 = pbias[c], b1 = pbias[c + 1];
            float v0 = (acc[t][j][0] + b0) * dl;
            float v1 = (acc[t][j][1] + b1) * dl;
            float v2 = (acc[t][j][2] + b0) * dh;
            float v3 = (acc[t][j][3] + b1) * dh;
            acc[t][j][0] = v0; acc[t][j][1] = v1;
            acc[t][j][2] = v2; acc[t][j][3] = v3;
            s0 += v0 + v1; q0 += v0 * v0 + v1 * v1;
            s1 += v2 + v3; q1 += v2 * v2 + v3 * v3;
        }
        #pragma unroll
        for (int o = 1; o <= 2; o <<= 1) {
            s0 += __shfl_xor_sync(0xffffffffu, s0, o);
            q0 += __shfl_xor_sync(0xffffffffu, q0, o);
            s1 += __shfl_xor_sync(0xffffffffu, s1, o);
            q1 += __shfl_xor_sync(0xffffffffu, q1, o);
        }
        if (ti == 0) {
            red[(rloc * NW + nw) * 2 + 0] = s0;
            red[(rloc * NW + nw) * 2 + 1] = q0;
            red[((rloc + 8) * NW + nw) * 2 + 0] = s1;
            red[((rloc + 8) * NW + nw) * 2 + 1] = q1;
        }
    }
    __syncthreads();
    #pragma unroll
    for (int t = 0; t < 4; t++) {
        int rloc = mw * 64 + t * 16 + g;
        float s0 = 0.f, q0 = 0.f, s1 = 0.f, q1 = 0.f;
        #pragma unroll
        for (int k = 0; k < NW; k++) {
            s0 += red[(rloc * NW + k) * 2 + 0];
            q0 += red[(rloc * NW + k) * 2 + 1];
            s1 += red[((rloc + 8) * NW + k) * 2 + 0];
            q1 += red[((rloc + 8) * NW + k) * 2 + 1];
        }
        float m0 = s0 * (1.0f / N), m1 = s1 * (1.0f / N);
        mul[t] = m0; muh[t] = m1;
        invl[t] = rsqrtf(q0 * (1.0f / N) - m0 * m0 + 1e-5f);
        invh[t] = rsqrtf(q1 * (1.0f / N) - m1 * m1 + 1e-5f);
    }
    const float alpha = __ldg(alp);
    #pragma unroll
    for (int t = 0; t < 4; t++) {
        int rl = mbase + mw * 64 + t * 16 + g;
        int rh = rl + 8;
        #pragma unroll
        for (int j = 0; j < 8; j++) {
            int c = nw * 64 + j * 8 + ti * 2;
            float g0 = pgam[c], g1 = pgam[c + 1];
            float e0 = pbet[c], e1 = pbet[c + 1];
            float y0 = g0 * (acc[t][j][0] - mul[t]) * invl[t] + e0;
            float y1 = g1 * (acc[t][j][1] - mul[t]) * invl[t] + e1;
            float y2 = g0 * (acc[t][j][2] - muh[t]) * invh[t] + e0;
            float y3 = g1 * (acc[t][j][3] - muh[t]) * invh[t] + e1;
            y0 = (y0 >= 0.f) ? y0 : alpha * y0;
            y1 = (y1 >= 0.f) ? y1 : alpha * y1;
            y2 = (y2 >= 0.f) ? y2 : alpha * y2;
            y3 = (y3 >= 0.f) ? y3 : alpha * y3;
            if (EPI == 1) {
                if (rl < NN) *(float2*)(Cf + (size_t)rl * N + c) = make_float2(y0, y1);
                if (rh < NN) *(float2*)(Cf + (size_t)rh * N + c) = make_float2(y2, y3);
            } else {
                u32 h01, l01, h23, l23;
                bsplit2(y0, y1, h01, l01);
                bsplit2(y2, y3, h23, l23);
                if (rl < NN) {
                    *(u32*)(Chi + (size_t)rl * N + c) = h01;
                    *(u32*)(Clo + (size_t)rl * N + c) = l01;
                }
                if (rh < NN) {
                    *(u32*)(Chi + (size_t)rh * N + c) = h23;
                    *(u32*)(Clo + (size_t)rh * N + c) = l23;
                }
            }
        }
    }
}

// ---------------- launch ----------------
extern "C" void kernel_launch(void* const* d_in, const int* in_sizes, int n_in,
                              void* d_out, int out_size) {
    const float* feat = (const float*)d_in[0];
    const float* W1 = (const float*)d_in[1];  const float* b1 = (const float*)d_in[2];
    const float* g1 = (const float*)d_in[3];  const float* be1 = (const float*)d_in[4];
    const float* a1 = (const float*)d_in[5];
    const float* W2 = (const float*)d_in[6];  const float* b2 = (const float*)d_in[7];
    const float* g2 = (const float*)d_in[8];  const float* be2 = (const float*)d_in[9];
    const float* a2 = (const float*)d_in[10];
    const float* W3 = (const float*)d_in[11]; const float* b3 = (const float*)d_in[12];
    const int* src = (const int*)d_in[13];
    const int* dst = (const int*)d_in[14];
    float* out = (float*)d_out;

    void* p;
    cudaGetSymbolAddress(&p, g_bufA);  float* bufA = (float*)p;
    cudaGetSymbolAddress(&p, g_h1);    __nv_bfloat16* h1 = (__nv_bfloat16*)p;
    cudaGetSymbolAddress(&p, g_l1);    __nv_bfloat16* l1 = (__nv_bfloat16*)p;
    cudaGetSymbolAddress(&p, g_h2);    __nv_bfloat16* h2 = (__nv_bfloat16*)p;
    cudaGetSymbolAddress(&p, g_l2);    __nv_bfloat16* l2 = (__nv_bfloat16*)p;
    cudaGetSymbolAddress(&p, g_w1h);   __nv_bfloat16* w1h = (__nv_bfloat16*)p;
    cudaGetSymbolAddress(&p, g_w1l);   __nv_bfloat16* w1l = (__nv_bfloat16*)p;
    cudaGetSymbolAddress(&p, g_w2h);   __nv_bfloat16* w2h = (__nv_bfloat16*)p;
    cudaGetSymbolAddress(&p, g_w2l);   __nv_bfloat16* w2l = (__nv_bfloat16*)p;
    cudaGetSymbolAddress(&p, g_w3h);   __nv_bfloat16* w3h = (__nv_bfloat16*)p;
    cudaGetSymbolAddress(&p, g_w3l);   __nv_bfloat16* w3l = (__nv_bfloat16*)p;

    // smem: 2 stages of 80*(BM+N)*2 = 122880, + 3*N floats params
    constexpr int SM1 = 2 * 80 * (128 + 256) * 2 + 3 * 256 * 4;  // 125952
    constexpr int SM3 = 2 * 80 * (256 + 128) * 2 + 3 * 128 * 4;  // 124416
    cudaFuncSetAttribute(k_mmagemm<128, 128, 256, 1>, cudaFuncAttributeMaxDynamicSharedMemorySize, SM1);
    cudaFuncSetAttribute(k_mmagemm<256, 128, 256, 2>, cudaFuncAttributeMaxDynamicSharedMemorySize, SM1);
    cudaFuncSetAttribute(k_mmagemm<256, 256, 128, 0>, cudaFuncAttributeMaxDynamicSharedMemorySize, SM3);

    // degree + CSR
    k_zero<<<(NN + 255) / 256, 256>>>();
    k_deg<<<(EE + 255) / 256, 256>>>(src, dst);
    k_norm<<<(NN + 255) / 256, 256>>>();
    k_part<<<NSB, 256>>>();
    k_pscan<<<1, 128>>>();
    k_scat<<<NSB, 1024>>>();
    k_fill<<<(EE + 255) / 256, 256>>>(src, dst);

    // weight transpose + split
    k_wsplit<<<(128 * 256 + 255) / 256, 256>>>(W1, w1h, w1l, 128, 256);
    k_wsplit<<<(256 * 256 + 255) / 256, 256>>>(W2, w2h, w2l, 256, 256);
    k_wsplit<<<(256 * 128 + 255) / 256, 256>>>(W3, w3h, w3l, 256, 128);

    // layer 1: agg(feat) -> split ; GEMM 128->256 + LN epilogue -> f32
    k_agg<128, 1><<<(NN + 7) / 8, 256>>>(feat, h1, l1, nullptr, nullptr);
    k_mmagemm<128, 128, 256, 1><<<(NN + 127) / 128, 256, SM1>>>(
        h1, l1, w1h, w1l, b1, g1, be1, a1, bufA, nullptr, nullptr);

    // layer 2: agg -> split ; GEMM 256->256 + LN epilogue -> bf16 split
    k_agg<256, 1><<<(NN + 7) / 8, 256>>>(bufA, h1, l1, nullptr, nullptr);
    k_mmagemm<256, 128, 256, 2><<<(NN + 127) / 128, 256, SM1>>>(
        h1, l1, w2h, w2l, b2, g2, be2, a2, nullptr, h2, l2);

    // layer 3: GEMM 256->128 raw -> f32 ; agg final with (x+b3)*deg_in
    k_mmagemm<256, 256, 128, 0><<<(NN + 255) / 256, 256, SM3>>>(
        h2, l2, w3h, w3l, nullptr, nullptr, nullptr, nullptr, bufA, nullptr, nullptr);
    k_agg<128, 2><<<(NN + 7) / 8, 256>>>(bufA, nullptr, nullptr, out, b3);
}

// round 5
// speedup vs baseline: 1.7419x; 1.0852x over previous
#include <cuda_runtime.h>
#include <cuda_bf16.h>
#include <cuda_fp16.h>
#include <cstdint>

#define NN 100000
#define EE 1600000
#define NSB 98            // ceil(NN/1024)
typedef unsigned long long u64;
typedef unsigned int u32;

// ---------------- device scratch ----------------
__device__ float g_bufA[(size_t)NN * 256];
__device__ __half g_f16[(size_t)NN * 128];    // feat in fp16
__device__ __half g_hh[(size_t)NN * 256];     // h1 in fp16
__device__ __nv_bfloat16 g_h1[(size_t)NN * 256];
__device__ __nv_bfloat16 g_l1[(size_t)NN * 256];
__device__ __nv_bfloat16 g_h2[(size_t)NN * 256];
__device__ __nv_bfloat16 g_l2[(size_t)NN * 256];
__device__ __nv_bfloat16 g_w1h[256 * 128], g_w1l[256 * 128];
__device__ __nv_bfloat16 g_w2h[256 * 256], g_w2l[256 * 256];
__device__ __nv_bfloat16 g_w3h[128 * 256], g_w3l[128 * 256];
__device__ float g_dno[NN], g_dni[NN];
__device__ int g_cout[NN], g_cin[NN];
__device__ int g_ptr[NN + 1], g_cur[NN], g_csrc[EE];
__device__ int g_part[128], g_poff[128];

// ---------------- helpers ----------------
__device__ __forceinline__ u32 pkbf(float a, float b) {
    __nv_bfloat16 ha = __float2bfloat16(a), hb = __float2bfloat16(b);
    unsigned short ua = *(unsigned short*)&ha, ub = *(unsigned short*)&hb;
    return ((u32)ub << 16) | (u32)ua;
}
__device__ __forceinline__ void bsplit2(float a, float b, u32& h, u32& l) {
    __nv_bfloat16 ha = __float2bfloat16(a), hb = __float2bfloat16(b);
    h = ((u32)(*(unsigned short*)&hb) << 16) | (u32)(*(unsigned short*)&ha);
    l = pkbf(a - __bfloat162float(ha), b - __bfloat162float(hb));
}
__device__ __forceinline__ void fma4(float4& a, float w, const float4 v) {
    a.x = fmaf(w, v.x, a.x); a.y = fmaf(w, v.y, a.y);
    a.z = fmaf(w, v.z, a.z); a.w = fmaf(w, v.w, a.w);
}
__device__ __forceinline__ void fmah4(float4& a, float w, const uint2 v) {
    __half2 h0 = *(__half2*)&v.x, h1 = *(__half2*)&v.y;
    float2 f0 = __half22float2(h0), f1 = __half22float2(h1);
    a.x = fmaf(w, f0.x, a.x); a.y = fmaf(w, f0.y, a.y);
    a.z = fmaf(w, f1.x, a.z); a.w = fmaf(w, f1.y, a.w);
}
__device__ __forceinline__ void mma16816(float* c, const u32* a, const u32* b) {
    asm volatile(
        "mma.sync.aligned.m16n8k16.row.col.f32.bf16.bf16.f32 "
        "{%0,%1,%2,%3},{%4,%5,%6,%7},{%8,%9},{%0,%1,%2,%3};"
        : "+f"(c[0]), "+f"(c[1]), "+f"(c[2]), "+f"(c[3])
        : "r"(a[0]), "r"(a[1]), "r"(a[2]), "r"(a[3]), "r"(b[0]), "r"(b[1]));
}
__device__ __forceinline__ void cpa16(void* s, const void* g) {
    u32 sa = (u32)__cvta_generic_to_shared(s);
    asm volatile("cp.async.cg.shared.global [%0], [%1], 16;" :: "r"(sa), "l"(g));
}
__device__ __forceinline__ void ldsm4(u32* r, u32 a) {
    asm volatile("ldmatrix.sync.aligned.m8n8.x4.shared.b16 {%0,%1,%2,%3},[%4];"
                 : "=r"(r[0]), "=r"(r[1]), "=r"(r[2]), "=r"(r[3]) : "r"(a));
}
__device__ __forceinline__ void ldsm2(u32* r, u32 a) {
    asm volatile("ldmatrix.sync.aligned.m8n8.x2.shared.b16 {%0,%1},[%2];"
                 : "=r"(r[0]), "=r"(r[1]) : "r"(a));
}

// ---------------- prep ----------------
__global__ void k_zero() {
    int i = blockIdx.x * blockDim.x + threadIdx.x;
    if (i < NN) { g_cout[i] = 0; g_cin[i] = 0; }
}
__global__ void k_deg(const int* __restrict__ src, const int* __restrict__ dst) {
    int i = blockIdx.x * blockDim.x + threadIdx.x;
    if (i < EE) {
        atomicAdd(&g_cout[src[i]], 1);
        atomicAdd(&g_cin[dst[i]], 1);
    }
}
__global__ void k_norm() {
    int i = blockIdx.x * blockDim.x + threadIdx.x;
    if (i < NN) {
        int co = g_cout[i]; if (co < 1) co = 1;
        int ci = g_cin[i];  if (ci < 1) ci = 1;
        g_dno[i] = rsqrtf((float)co);
        g_dni[i] = rsqrtf((float)ci);
    }
}
__global__ void k_part() {
    int b = blockIdx.x, tid = threadIdx.x;
    int s = 0;
    for (int j = tid; j < 1024; j += 256) {
        int i = b * 1024 + j;
        s += (i < NN) ? g_cin[i] : 0;
    }
    #pragma unroll
    for (int o = 16; o; o >>= 1) s += __shfl_xor_sync(0xffffffffu, s, o);
    __shared__ int sh[8];
    if ((tid & 31) == 0) sh[tid >> 5] = s;
    __syncthreads();
    if (tid == 0) {
        int t = 0;
        #pragma unroll
        for (int j = 0; j < 8; j++) t += sh[j];
        g_part[b] = t;
    }
}
__global__ void k_pscan() {
    __shared__ int ws[4], ws2[4];
    int tid = threadIdx.x, lane = tid & 31, w = tid >> 5;
    int v = (tid < NSB) ? g_part[tid] : 0;
    int x = v;
    #pragma unroll
    for (int o = 1; o < 32; o <<= 1) {
        int t = __shfl_up_sync(0xffffffffu, x, o);
        if (lane >= o) x += t;
    }
    if (lane == 31) ws[w] = x;
    __syncthreads();
    if (tid == 0) {
        int run = 0;
        #pragma unroll
        for (int j = 0; j < 4; j++) { ws2[j] = run; run += ws[j]; }
    }
    __syncthreads();
    if (tid < NSB) g_poff[tid] = ws2[w] + x - v;
}
__global__ void k_scat() {
    __shared__ int ws[32];
    int b = blockIdx.x, tid = threadIdx.x;
    int lane = tid & 31, w = tid >> 5;
    int i = b * 1024 + tid;
    int v = (i < NN) ? g_cin[i] : 0;
    int x = v;
    #pragma unroll
    for (int o = 1; o < 32; o <<= 1) {
        int t = __shfl_up_sync(0xffffffffu, x, o);
        if (lane >= o) x += t;
    }
    if (lane == 31) ws[w] = x;
    __syncthreads();
    if (w == 0) {
        int s = ws[lane];
        #pragma unroll
        for (int o = 1; o < 32; o <<= 1) {
            int t = __shfl_up_sync(0xffffffffu, s, o);
            if (lane >= o) s += t;
        }
        ws[lane] = s;
    }
    __syncthreads();
    int pre = (w > 0) ? ws[w - 1] : 0;
    int exc = g_poff[b] + pre + x - v;
    if (i < NN) { g_ptr[i] = exc; g_cur[i] = exc; }
    if (b == 0 && tid == 0) g_ptr[NN] = EE;
}
__global__ void k_fill(const int* __restrict__ src, const int* __restrict__ dst) {
    int i = blockIdx.x * blockDim.x + threadIdx.x;
    if (i < EE) {
        int d = dst[i];
        int p = atomicAdd(&g_cur[d], 1);
        g_csrc[p] = src[i];
    }
}
// transpose + bf16-split weights: W[K,Nout] -> H/L[Nout,K]
__global__ void k_wsplit(const float* __restrict__ W, __nv_bfloat16* __restrict__ H,
                         __nv_bfloat16* __restrict__ L, int Kd, int Nout) {
    int i = blockIdx.x * blockDim.x + threadIdx.x;
    if (i < Kd * Nout) {
        int n = i / Kd, k = i % Kd;
        float v = W[(size_t)k * Nout + n];
        __nv_bfloat16 h = __float2bfloat16(v);
        float l = v - __bfloat162float(h);
        H[i] = h;
        L[i] = __float2bfloat16(l);
    }
}
// f32 -> fp16 conversion (vectorized)
__global__ void k_cvt16(const float* __restrict__ in, __half* __restrict__ out, int n4) {
    int i = blockIdx.x * blockDim.x + threadIdx.x;
    if (i < n4) {
        float4 v = ((const float4*)in)[i];
        __half2 a = __floats2half2_rn(v.x, v.y), b = __floats2half2_rn(v.z, v.w);
        ((uint2*)out)[i] = make_uint2(*(u32*)&a, *(u32*)&b);
    }
}

// ---------------- aggregation (warp-per-node, CSR) ----------------
// IN16: gather fp16 rows; else fp32.
// MODE 1: write bf16 hi/lo split; MODE 2: (acc+b3)*dni -> f32 out
template<int D, int MODE, int IN16>
__global__ void k_agg(const void* __restrict__ inv,
                      __nv_bfloat16* __restrict__ oh, __nv_bfloat16* __restrict__ ol,
                      float* __restrict__ of, const float* __restrict__ b3) {
    const int w = (blockIdx.x << 3) + (threadIdx.x >> 5);
    const int lane = threadIdx.x & 31;
    if (w >= NN) return;
    const int beg = g_ptr[w], end = g_ptr[w + 1];
    float4 a0 = make_float4(0.f, 0.f, 0.f, 0.f);
    float4 a1 = make_float4(0.f, 0.f, 0.f, 0.f);
    const float* inf = (const float*)inv;
    const __half* inh = (const __half*)inv;

    int e = beg;
    for (; e + 4 <= end; e += 4) {
        int s0 = g_csrc[e], s1 = g_csrc[e + 1];
        int s2 = g_csrc[e + 2], s3 = g_csrc[e + 3];
        float w0 = g_dno[s0], w1 = g_dno[s1];
        float w2 = g_dno[s2], w3 = g_dno[s3];
        if (IN16) {
            const uint2* r0 = (const uint2*)(inh + (size_t)s0 * D);
            const uint2* r1 = (const uint2*)(inh + (size_t)s1 * D);
            const uint2* r2 = (const uint2*)(inh + (size_t)s2 * D);
            const uint2* r3 = (const uint2*)(inh + (size_t)s3 * D);
            uint2 v0 = r0[lane], v1 = r1[lane], v2 = r2[lane], v3 = r3[lane];
            fmah4(a0, w0, v0); fmah4(a0, w1, v1); fmah4(a0, w2, v2); fmah4(a0, w3, v3);
            if (D == 256) {
                uint2 u0 = r0[lane + 32], u1 = r1[lane + 32];
                uint2 u2 = r2[lane + 32], u3 = r3[lane + 32];
                fmah4(a1, w0, u0); fmah4(a1, w1, u1); fmah4(a1, w2, u2); fmah4(a1, w3, u3);
            }
        } else {
            const float4* r0 = (const float4*)inf + (size_t)s0 * (D / 4);
            const float4* r1 = (const float4*)inf + (size_t)s1 * (D / 4);
            const float4* r2 = (const float4*)inf + (size_t)s2 * (D / 4);
            const float4* r3 = (const float4*)inf + (size_t)s3 * (D / 4);
            float4 v0 = r0[lane], v1 = r1[lane], v2 = r2[lane], v3 = r3[lane];
            fma4(a0, w0, v0); fma4(a0, w1, v1); fma4(a0, w2, v2); fma4(a0, w3, v3);
            if (D == 256) {
                float4 u0 = r0[lane + 32], u1 = r1[lane + 32];
                float4 u2 = r2[lane + 32], u3 = r3[lane + 32];
                fma4(a1, w0, u0); fma4(a1, w1, u1); fma4(a1, w2, u2); fma4(a1, w3, u3);
            }
        }
    }
    for (; e < end; e++) {
        int s0 = g_csrc[e];
        float w0 = g_dno[s0];
        if (IN16) {
            const uint2* r0 = (const uint2*)(inh + (size_t)s0 * D);
            fmah4(a0, w0, r0[lane]);
            if (D == 256) fmah4(a1, w0, r0[lane + 32]);
        } else {
            const float4* r0 = (const float4*)inf + (size_t)s0 * (D / 4);
            fma4(a0, w0, r0[lane]);
            if (D == 256) fma4(a1, w0, r0[lane + 32]);
        }
    }
    if (MODE == 1) {
        uint2 hv, lv;
        bsplit2(a0.x, a0.y, hv.x, lv.x);
        bsplit2(a0.z, a0.w, hv.y, lv.y);
        ((uint2*)(oh + (size_t)w * D))[lane] = hv;
        ((uint2*)(ol + (size_t)w * D))[lane] = lv;
        if (D == 256) {
            bsplit2(a1.x, a1.y, hv.x, lv.x);
            bsplit2(a1.z, a1.w, hv.y, lv.y);
            ((uint2*)(oh + (size_t)w * D))[lane + 32] = hv;
            ((uint2*)(ol + (size_t)w * D))[lane + 32] = lv;
        }
    } else {
        float4 bb = ((const float4*)b3)[lane];
        float d = g_dni[w];
        a0.x = (a0.x + bb.x) * d; a0.y = (a0.y + bb.y) * d;
        a0.z = (a0.z + bb.z) * d; a0.w = (a0.w + bb.w) * d;
        ((float4*)(of + (size_t)w * D))[lane] = a0;
    }
}

// ---------------- bf16-split GEMM via mma.sync (HMMA), cp.async 2-stage, ldmatrix ----
// C[BM/blk, N] = A[.,K] @ Wt[N,K]^T  using Ah*Bh + Ah*Bl + Al*Bh
// EPI 0: raw f32 ; 1: bias,deg,LN,PReLU -> fp16 ; 2: same -> bf16 split
template<int K, int BM, int N, int EPI>
__global__ void __launch_bounds__(256, 1)
k_mmagemm(const __nv_bfloat16* __restrict__ Ahi, const __nv_bfloat16* __restrict__ Alo,
          const __nv_bfloat16* __restrict__ Bhi, const __nv_bfloat16* __restrict__ Blo,
          const float* __restrict__ bias, const float* __restrict__ gam,
          const float* __restrict__ bet, const float* __restrict__ alp,
          float* __restrict__ Cf, __nv_bfloat16* __restrict__ Chi,
          __nv_bfloat16* __restrict__ Clo) {
    extern __shared__ char smem[];
    constexpr int MW = BM / 64;         // warp-rows
    constexpr int NW = N / 64;          // warp-cols
    static_assert(MW * NW == 8, "8 warps");
    constexpr int SA = 80;              // smem row stride (bytes) for 32-bf16 rows
    constexpr int STG = SA * (BM + N) * 2;    // one stage: Ah,Al,Bh,Bl
    constexpr int OAH = 0;
    constexpr int OAL = BM * SA;
    constexpr int OBH = 2 * BM * SA;
    constexpr int OBL = 2 * BM * SA + N * SA;
    constexpr int POFF = 2 * STG;
    float* pbias = (float*)(smem + POFF);
    float* pgam  = pbias + N;
    float* pbet  = pgam + N;

    const int tid = threadIdx.x;
    const int wid = tid >> 5, lane = tid & 31;
    const int g = lane >> 2, ti = lane & 3;
    const int mw = wid / NW, nw = wid % NW;
    const int mbase = blockIdx.x * BM;
    const u32 smem_u = (u32)__cvta_generic_to_shared(smem);

    // ldmatrix per-lane address components
    const int Lb = lane & 15;
    const u32 rA = (u32)(((lane & 7) + 8 * ((lane >> 3) & 1)) * SA + 16 * ((lane >> 4) & 1));
    const u32 rB = (u32)((Lb & 7) * SA + ((Lb >> 3) << 4));

    if (EPI >= 1) {
        for (int i = tid; i < N; i += 256) {
            pbias[i] = bias[i]; pgam[i] = gam[i]; pbet[i] = bet[i];
        }
    }

    float acc[4][8][4];
    #pragma unroll
    for (int t = 0; t < 4; t++)
        #pragma unroll
        for (int j = 0; j < 8; j++)
            #pragma unroll
            for (int q = 0; q < 4; q++) acc[t][j][q] = 0.f;

    auto issue_stage = [&](int it, int buf) {
        const int kb = it * 32;
        char* base = smem + buf * STG;
        #pragma unroll
        for (int i = tid; i < BM * 4; i += 256) {
            int r = i >> 2, q = i & 3;
            int rg = mbase + r; if (rg > NN - 1) rg = NN - 1;
            size_t go = (size_t)rg * K + kb + q * 8;
            cpa16(base + OAH + r * SA + q * 16, Ahi + go);
            cpa16(base + OAL + r * SA + q * 16, Alo + go);
        }
        #pragma unroll
        for (int i = tid; i < N * 4; i += 256) {
            int r = i >> 2, q = i & 3;
            size_t go = (size_t)r * K + kb + q * 8;
            cpa16(base + OBH + r * SA + q * 16, Bhi + go);
            cpa16(base + OBL + r * SA + q * 16, Blo + go);
        }
        asm volatile("cp.async.commit_group;" ::: "memory");
    };

    constexpr int NIT = K / 32;
    issue_stage(0, 0);
    for (int it = 0; it < NIT; it++) {
        const int buf = it & 1;
        if (it + 1 < NIT) {
            issue_stage(it + 1, buf ^ 1);
            asm volatile("cp.async.wait_group 1;" ::: "memory");
        } else {
            asm volatile("cp.async.wait_group 0;" ::: "memory");
        }
        __syncthreads();
        const u32 aAh = smem_u + buf * STG + OAH + (u32)((mw * 64) * SA) + rA;
        const u32 aAl = smem_u + buf * STG + OAL + (u32)((mw * 64) * SA) + rA;
        const u32 aBh = smem_u + buf * STG + OBH + (u32)((nw * 64) * SA) + rB;
        const u32 aBl = smem_u + buf * STG + OBL + (u32)((nw * 64) * SA) + rB;
        #pragma unroll
        for (int kt = 0; kt < 2; kt++) {
            const u32 kof = kt * 32;
            u32 ah[4][4], al[4][4];
            #pragma unroll
            for (int t = 0; t < 4; t++) {
                ldsm4(ah[t], aAh + (u32)(t * 16 * SA) + kof);
                ldsm4(al[t], aAl + (u32)(t * 16 * SA) + kof);
            }
            #pragma unroll
            for (int j = 0; j < 8; j++) {
                u32 bh[2], bl[2];
                ldsm2(bh, aBh + (u32)(j * 8 * SA) + kof);
                ldsm2(bl, aBl + (u32)(j * 8 * SA) + kof);
                #pragma unroll
                for (int t = 0; t < 4; t++) {
                    mma16816(acc[t][j], ah[t], bh);
                    mma16816(acc[t][j], ah[t], bl);
                    mma16816(acc[t][j], al[t], bh);
                }
            }
        }
        __syncthreads();
    }

    if (EPI == 0) {
        #pragma unroll
        for (int t = 0; t < 4; t++) {
            int rl = mbase + mw * 64 + t * 16 + g;
            int rh = rl + 8;
            #pragma unroll
            for (int j = 0; j < 8; j++) {
                int c = nw * 64 + j * 8 + ti * 2;
                if (rl < NN)
                    *(float2*)(Cf + (size_t)rl * N + c) = make_float2(acc[t][j][0], acc[t][j][1]);
                if (rh < NN)
                    *(float2*)(Cf + (size_t)rh * N + c) = make_float2(acc[t][j][2], acc[t][j][3]);
            }
        }
        return;
    }

    // fused epilogue: v=(acc+bias)*dni; LN; PReLU
    float* red = (float*)smem;  // [BM][NW][2], reuses tile smem
    float mul[4], invl[4], muh[4], invh[4];
    #pragma unroll
    for (int t = 0; t < 4; t++) {
        int rloc = mw * 64 + t * 16 + g;
        int rl = mbase + rloc, rh = rl + 8;
        float dl = g_dni[(rl < NN) ? rl : (NN - 1)];
        float dh = g_dni[(rh < NN) ? rh : (NN - 1)];
        float s0 = 0.f, q0 = 0.f, s1 = 0.f, q1 = 0.f;
        #pragma unroll
        for (int j = 0; j < 8; j++) {
            int c = nw * 64 + j * 8 + ti * 2;
            float b0 = pbias[c], b1 = pbias[c + 1];
            float v0 = (acc[t][j][0] + b0) * dl;
            float v1 = (acc[t][j][1] + b1) * dl;
            float v2 = (acc[t][j][2] + b0) * dh;
            float v3 = (acc[t][j][3] + b1) * dh;
            acc[t][j][0] = v0; acc[t][j][1] = v1;
            acc[t][j][2] = v2; acc[t][j][3] = v3;
            s0 += v0 + v1; q0 += v0 * v0 + v1 * v1;
            s1 += v2 + v3; q1 += v2 * v2 + v3 * v3;
        }
        #pragma unroll
        for (int o = 1; o <= 2; o <<= 1) {
            s0 += __shfl_xor_sync(0xffffffffu, s0, o);
            q0 += __shfl_xor_sync(0xffffffffu, q0, o);
            s1 += __shfl_xor_sync(0xffffffffu, s1, o);
            q1 += __shfl_xor_sync(0xffffffffu, q1, o);
        }
        if (ti == 0) {
            red[(rloc * NW + nw) * 2 + 0] = s0;
            red[(rloc * NW + nw) * 2 + 1] = q0;
            red[((rloc + 8) * NW + nw) * 2 + 0] = s1;
            red[((rloc + 8) * NW + nw) * 2 + 1] = q1;
        }
    }
    __syncthreads();
    #pragma unroll
    for (int t = 0; t < 4; t++) {
        int rloc = mw * 64 + t * 16 + g;
        float s0 = 0.f, q0 = 0.f, s1 = 0.f, q1 = 0.f;
        #pragma unroll
        for (int k = 0; k < NW; k++) {
            s0 += red[(rloc * NW + k) * 2 + 0];
            q0 += red[(rloc * NW + k) * 2 + 1];
            s1 += red[((rloc + 8) * NW + k) * 2 + 0];
            q1 += red[((rloc + 8) * NW + k) * 2 + 1];
        }
        float m0 = s0 * (1.0f / N), m1 = s1 * (1.0f / N);
        mul[t] = m0; muh[t] = m1;
        invl[t] = rsqrtf(q0 * (1.0f / N) - m0 * m0 + 1e-5f);
        invh[t] = rsqrtf(q1 * (1.0f / N) - m1 * m1 + 1e-5f);
    }
    const float alpha = __ldg(alp);
    #pragma unroll
    for (int t = 0; t < 4; t++) {
        int rl = mbase + mw * 64 + t * 16 + g;
        int rh = rl + 8;
        #pragma unroll
        for (int j = 0; j < 8; j++) {
            int c = nw * 64 + j * 8 + ti * 2;
            float g0 = pgam[c], g1 = pgam[c + 1];
            float e0 = pbet[c], e1 = pbet[c + 1];
            float y0 = g0 * (acc[t][j][0] - mul[t]) * invl[t] + e0;
            float y1 = g1 * (acc[t][j][1] - mul[t]) * invl[t] + e1;
            float y2 = g0 * (acc[t][j][2] - muh[t]) * invh[t] + e0;
            float y3 = g1 * (acc[t][j][3] - muh[t]) * invh[t] + e1;
            y0 = (y0 >= 0.f) ? y0 : alpha * y0;
            y1 = (y1 >= 0.f) ? y1 : alpha * y1;
            y2 = (y2 >= 0.f) ? y2 : alpha * y2;
            y3 = (y3 >= 0.f) ? y3 : alpha * y3;
            if (EPI == 1) {
                __half* Ch = (__half*)Cf;
                if (rl < NN)
                    *(__half2*)(Ch + (size_t)rl * N + c) = __floats2half2_rn(y0, y1);
                if (rh < NN)
                    *(__half2*)(Ch + (size_t)rh * N + c) = __floats2half2_rn(y2, y3);
            } else {
                u32 h01, l01, h23, l23;
                bsplit2(y0, y1, h01, l01);
                bsplit2(y2, y3, h23, l23);
                if (rl < NN) {
                    *(u32*)(Chi + (size_t)rl * N + c) = h01;
                    *(u32*)(Clo + (size_t)rl * N + c) = l01;
                }
                if (rh < NN) {
                    *(u32*)(Chi + (size_t)rh * N + c) = h23;
                    *(u32*)(Clo + (size_t)rh * N + c) = l23;
                }
            }
        }
    }
}

// ---------------- launch ----------------
extern "C" void kernel_launch(void* const* d_in, const int* in_sizes, int n_in,
                              void* d_out, int out_size) {
    const float* feat = (const float*)d_in[0];
    const float* W1 = (const float*)d_in[1];  const float* b1 = (const float*)d_in[2];
    const float* g1 = (const float*)d_in[3];  const float* be1 = (const float*)d_in[4];
    const float* a1 = (const float*)d_in[5];
    const float* W2 = (const float*)d_in[6];  const float* b2 = (const float*)d_in[7];
    const float* g2 = (const float*)d_in[8];  const float* be2 = (const float*)d_in[9];
    const float* a2 = (const float*)d_in[10];
    const float* W3 = (const float*)d_in[11]; const float* b3 = (const float*)d_in[12];
    const int* src = (const int*)d_in[13];
    const int* dst = (const int*)d_in[14];
    float* out = (float*)d_out;

    void* p;
    cudaGetSymbolAddress(&p, g_bufA);  float* bufA = (float*)p;
    cudaGetSymbolAddress(&p, g_f16);   __half* f16 = (__half*)p;
    cudaGetSymbolAddress(&p, g_hh);    __half* hh = (__half*)p;
    cudaGetSymbolAddress(&p, g_h1);    __nv_bfloat16* h1 = (__nv_bfloat16*)p;
    cudaGetSymbolAddress(&p, g_l1);    __nv_bfloat16* l1 = (__nv_bfloat16*)p;
    cudaGetSymbolAddress(&p, g_h2);    __nv_bfloat16* h2 = (__nv_bfloat16*)p;
    cudaGetSymbolAddress(&p, g_l2);    __nv_bfloat16* l2 = (__nv_bfloat16*)p;
    cudaGetSymbolAddress(&p, g_w1h);   __nv_bfloat16* w1h = (__nv_bfloat16*)p;
    cudaGetSymbolAddress(&p, g_w1l);   __nv_bfloat16* w1l = (__nv_bfloat16*)p;
    cudaGetSymbolAddress(&p, g_w2h);   __nv_bfloat16* w2h = (__nv_bfloat16*)p;
    cudaGetSymbolAddress(&p, g_w2l);   __nv_bfloat16* w2l = (__nv_bfloat16*)p;
    cudaGetSymbolAddress(&p, g_w3h);   __nv_bfloat16* w3h = (__nv_bfloat16*)p;
    cudaGetSymbolAddress(&p, g_w3l);   __nv_bfloat16* w3l = (__nv_bfloat16*)p;

    // smem: 2 stages of 80*(BM+N)*2 = 122880, + 3*N floats params
    constexpr int SM1 = 2 * 80 * (128 + 256) * 2 + 3 * 256 * 4;  // 125952
    constexpr int SM3 = 2 * 80 * (256 + 128) * 2 + 3 * 128 * 4;  // 124416
    cudaFuncSetAttribute(k_mmagemm<128, 128, 256, 1>, cudaFuncAttributeMaxDynamicSharedMemorySize, SM1);
    cudaFuncSetAttribute(k_mmagemm<256, 128, 256, 2>, cudaFuncAttributeMaxDynamicSharedMemorySize, SM1);
    cudaFuncSetAttribute(k_mmagemm<256, 256, 128, 0>, cudaFuncAttributeMaxDynamicSharedMemorySize, SM3);

    // degree + CSR
    k_zero<<<(NN + 255) / 256, 256>>>();
    k_deg<<<(EE + 255) / 256, 256>>>(src, dst);
    k_norm<<<(NN + 255) / 256, 256>>>();
    k_part<<<NSB, 256>>>();
    k_pscan<<<1, 128>>>();
    k_scat<<<NSB, 1024>>>();
    k_fill<<<(EE + 255) / 256, 256>>>(src, dst);

    // weight transpose + split ; feat -> fp16
    k_wsplit<<<(128 * 256 + 255) / 256, 256>>>(W1, w1h, w1l, 128, 256);
    k_wsplit<<<(256 * 256 + 255) / 256, 256>>>(W2, w2h, w2l, 256, 256);
    k_wsplit<<<(256 * 128 + 255) / 256, 256>>>(W3, w3h, w3l, 256, 128);
    k_cvt16<<<(NN * 128 / 4 + 255) / 256, 256>>>(feat, f16, NN * 128 / 4);

    // layer 1: agg(feat16) -> split ; GEMM 128->256 + LN epilogue -> fp16
    k_agg<128, 1, 1><<<(NN + 7) / 8, 256>>>(f16, h1, l1, nullptr, nullptr);
    k_mmagemm<128, 128, 256, 1><<<(NN + 127) / 128, 256, SM1>>>(
        h1, l1, w1h, w1l, b1, g1, be1, a1, (float*)hh, nullptr, nullptr);

    // layer 2: agg(fp16) -> split ; GEMM 256->256 + LN epilogue -> bf16 split
    k_agg<256, 1, 1><<<(NN + 7) / 8, 256>>>(hh, h1, l1, nullptr, nullptr);
    k_mmagemm<256, 128, 256, 2><<<(NN + 127) / 128, 256, SM1>>>(
        h1, l1, w2h, w2l, b2, g2, be2, a2, nullptr, h2, l2);

    // layer 3: GEMM 256->128 raw -> f32 ; agg final (fp32) with (x+b3)*deg_in
    k_mmagemm<256, 256, 128, 0><<<(NN + 255) / 256, 256, SM3>>>(
        h2, l2, w3h, w3l, nullptr, nullptr, nullptr, nullptr, bufA, nullptr, nullptr);
    k_agg<128, 2, 0><<<(NN + 7) / 8, 256>>>(bufA, nullptr, nullptr, out, b3);
}

// round 6
// speedup vs baseline: 2.1508x; 1.2347x over previous
#include <cuda_runtime.h>
#include <cuda_fp16.h>
#include <cstdint>

#define NN 100000
#define EE 1600000
#define NSB 98            // ceil(NN/1024)
typedef unsigned long long u64;
typedef unsigned int u32;

// ---------------- device scratch ----------------
__device__ __half g_f16[(size_t)NN * 128];    // feat fp16
__device__ __half g_a16[(size_t)NN * 256];    // agg output fp16
__device__ __half g_hh[(size_t)NN * 256];     // L1 gemm out fp16
__device__ __half g_p16[(size_t)NN * 256];    // L2 gemm out fp16
__device__ __half g_q16[(size_t)NN * 128];    // L3 gemm out fp16
__device__ __half g_w1h[256 * 128], g_w1l[256 * 128];
__device__ __half g_w2h[256 * 256], g_w2l[256 * 256];
__device__ __half g_w3h[128 * 256], g_w3l[128 * 256];
__device__ float g_dno[NN], g_dni[NN];
__device__ int g_cout[NN], g_cin[NN];
__device__ int g_ptr[NN + 1], g_cur[NN], g_csrc[EE];
__device__ int g_part[128], g_poff[128];

// ---------------- helpers ----------------
__device__ __forceinline__ void fmah4(float4& a, float w, const uint2 v) {
    __half2 h0 = *(__half2*)&v.x, h1 = *(__half2*)&v.y;
    float2 f0 = __half22float2(h0), f1 = __half22float2(h1);
    a.x = fmaf(w, f0.x, a.x); a.y = fmaf(w, f0.y, a.y);
    a.z = fmaf(w, f1.x, a.z); a.w = fmaf(w, f1.y, a.w);
}
__device__ __forceinline__ void mma16816(float* c, const u32* a, const u32* b) {
    asm volatile(
        "mma.sync.aligned.m16n8k16.row.col.f32.f16.f16.f32 "
        "{%0,%1,%2,%3},{%4,%5,%6,%7},{%8,%9},{%0,%1,%2,%3};"
        : "+f"(c[0]), "+f"(c[1]), "+f"(c[2]), "+f"(c[3])
        : "r"(a[0]), "r"(a[1]), "r"(a[2]), "r"(a[3]), "r"(b[0]), "r"(b[1]));
}
__device__ __forceinline__ void cpa16(void* s, const void* g) {
    u32 sa = (u32)__cvta_generic_to_shared(s);
    asm volatile("cp.async.cg.shared.global [%0], [%1], 16;" :: "r"(sa), "l"(g));
}
__device__ __forceinline__ void ldsm4(u32* r, u32 a) {
    asm volatile("ldmatrix.sync.aligned.m8n8.x4.shared.b16 {%0,%1,%2,%3},[%4];"
                 : "=r"(r[0]), "=r"(r[1]), "=r"(r[2]), "=r"(r[3]) : "r"(a));
}
__device__ __forceinline__ void ldsm2(u32* r, u32 a) {
    asm volatile("ldmatrix.sync.aligned.m8n8.x2.shared.b16 {%0,%1},[%2];"
                 : "=r"(r[0]), "=r"(r[1]) : "r"(a));
}

// ---------------- prep ----------------
__global__ void k_zero() {
    int i = blockIdx.x * blockDim.x + threadIdx.x;
    if (i < NN) { g_cout[i] = 0; g_cin[i] = 0; }
}
__global__ void k_deg(const int* __restrict__ src, const int* __restrict__ dst) {
    int i = blockIdx.x * blockDim.x + threadIdx.x;
    if (i < EE) {
        atomicAdd(&g_cout[src[i]], 1);
        atomicAdd(&g_cin[dst[i]], 1);
    }
}
__global__ void k_norm() {
    int i = blockIdx.x * blockDim.x + threadIdx.x;
    if (i < NN) {
        int co = g_cout[i]; if (co < 1) co = 1;
        int ci = g_cin[i];  if (ci < 1) ci = 1;
        g_dno[i] = rsqrtf((float)co);
        g_dni[i] = rsqrtf((float)ci);
    }
}
__global__ void k_part() {
    int b = blockIdx.x, tid = threadIdx.x;
    int s = 0;
    for (int j = tid; j < 1024; j += 256) {
        int i = b * 1024 + j;
        s += (i < NN) ? g_cin[i] : 0;
    }
    #pragma unroll
    for (int o = 16; o; o >>= 1) s += __shfl_xor_sync(0xffffffffu, s, o);
    __shared__ int sh[8];
    if ((tid & 31) == 0) sh[tid >> 5] = s;
    __syncthreads();
    if (tid == 0) {
        int t = 0;
        #pragma unroll
        for (int j = 0; j < 8; j++) t += sh[j];
        g_part[b] = t;
    }
}
__global__ void k_pscan() {
    __shared__ int ws[4], ws2[4];
    int tid = threadIdx.x, lane = tid & 31, w = tid >> 5;
    int v = (tid < NSB) ? g_part[tid] : 0;
    int x = v;
    #pragma unroll
    for (int o = 1; o < 32; o <<= 1) {
        int t = __shfl_up_sync(0xffffffffu, x, o);
        if (lane >= o) x += t;
    }
    if (lane == 31) ws[w] = x;
    __syncthreads();
    if (tid == 0) {
        int run = 0;
        #pragma unroll
        for (int j = 0; j < 4; j++) { ws2[j] = run; run += ws[j]; }
    }
    __syncthreads();
    if (tid < NSB) g_poff[tid] = ws2[w] + x - v;
}
__global__ void k_scat() {
    __shared__ int ws[32];
    int b = blockIdx.x, tid = threadIdx.x;
    int lane = tid & 31, w = tid >> 5;
    int i = b * 1024 + tid;
    int v = (i < NN) ? g_cin[i] : 0;
    int x = v;
    #pragma unroll
    for (int o = 1; o < 32; o <<= 1) {
        int t = __shfl_up_sync(0xffffffffu, x, o);
        if (lane >= o) x += t;
    }
    if (lane == 31) ws[w] = x;
    __syncthreads();
    if (w == 0) {
        int s = ws[lane];
        #pragma unroll
        for (int o = 1; o < 32; o <<= 1) {
            int t = __shfl_up_sync(0xffffffffu, s, o);
            if (lane >= o) s += t;
        }
        ws[lane] = s;
    }
    __syncthreads();
    int pre = (w > 0) ? ws[w - 1] : 0;
    int exc = g_poff[b] + pre + x - v;
    if (i < NN) { g_ptr[i] = exc; g_cur[i] = exc; }
    if (b == 0 && tid == 0) g_ptr[NN] = EE;
}
__global__ void k_fill(const int* __restrict__ src, const int* __restrict__ dst) {
    int i = blockIdx.x * blockDim.x + threadIdx.x;
    if (i < EE) {
        int d = dst[i];
        int p = atomicAdd(&g_cur[d], 1);
        g_csrc[p] = src[i];
    }
}
// transpose + fp16-split weights: W[K,Nout] -> H/L[Nout,K]
__global__ void k_wsplit(const float* __restrict__ W, __half* __restrict__ H,
                         __half* __restrict__ L, int Kd, int Nout) {
    int i = blockIdx.x * blockDim.x + threadIdx.x;
    if (i < Kd * Nout) {
        int n = i / Kd, k = i % Kd;
        float v = W[(size_t)k * Nout + n];
        __half h = __float2half_rn(v);
        H[i] = h;
        L[i] = __float2half_rn(v - __half2float(h));
    }
}
// f32 -> fp16 conversion (vectorized)
__global__ void k_cvt16(const float* __restrict__ in, __half* __restrict__ out, int n4) {
    int i = blockIdx.x * blockDim.x + threadIdx.x;
    if (i < n4) {
        float4 v = ((const float4*)in)[i];
        __half2 a = __floats2half2_rn(v.x, v.y), b = __floats2half2_rn(v.z, v.w);
        ((uint2*)out)[i] = make_uint2(*(u32*)&a, *(u32*)&b);
    }
}

// ---------------- aggregation (warp-per-node, CSR, fp16 gather) ----------------
// MODE 1: write fp16; MODE 2: (acc+b3)*dni -> f32 out
template<int D, int MODE>
__global__ void k_agg(const __half* __restrict__ in,
                      __half* __restrict__ oh, float* __restrict__ of,
                      const float* __restrict__ b3) {
    const int w = (blockIdx.x << 3) + (threadIdx.x >> 5);
    const int lane = threadIdx.x & 31;
    if (w >= NN) return;
    const int beg = g_ptr[w], end = g_ptr[w + 1];
    float4 a0 = make_float4(0.f, 0.f, 0.f, 0.f);
    float4 a1 = make_float4(0.f, 0.f, 0.f, 0.f);

    int e = beg;
    for (; e + 4 <= end; e += 4) {
        int s0 = g_csrc[e], s1 = g_csrc[e + 1];
        int s2 = g_csrc[e + 2], s3 = g_csrc[e + 3];
        float w0 = g_dno[s0], w1 = g_dno[s1];
        float w2 = g_dno[s2], w3 = g_dno[s3];
        const uint2* r0 = (const uint2*)(in + (size_t)s0 * D);
        const uint2* r1 = (const uint2*)(in + (size_t)s1 * D);
        const uint2* r2 = (const uint2*)(in + (size_t)s2 * D);
        const uint2* r3 = (const uint2*)(in + (size_t)s3 * D);
        uint2 v0 = r0[lane], v1 = r1[lane], v2 = r2[lane], v3 = r3[lane];
        fmah4(a0, w0, v0); fmah4(a0, w1, v1); fmah4(a0, w2, v2); fmah4(a0, w3, v3);
        if (D == 256) {
            uint2 u0 = r0[lane + 32], u1 = r1[lane + 32];
            uint2 u2 = r2[lane + 32], u3 = r3[lane + 32];
            fmah4(a1, w0, u0); fmah4(a1, w1, u1); fmah4(a1, w2, u2); fmah4(a1, w3, u3);
        }
    }
    for (; e < end; e++) {
        int s0 = g_csrc[e];
        float w0 = g_dno[s0];
        const uint2* r0 = (const uint2*)(in + (size_t)s0 * D);
        fmah4(a0, w0, r0[lane]);
        if (D == 256) fmah4(a1, w0, r0[lane + 32]);
    }
    if (MODE == 1) {
        __half2 h0 = __floats2half2_rn(a0.x, a0.y), h1 = __floats2half2_rn(a0.z, a0.w);
        ((uint2*)(oh + (size_t)w * D))[lane] = make_uint2(*(u32*)&h0, *(u32*)&h1);
        if (D == 256) {
            h0 = __floats2half2_rn(a1.x, a1.y); h1 = __floats2half2_rn(a1.z, a1.w);
            ((uint2*)(oh + (size_t)w * D))[lane + 32] = make_uint2(*(u32*)&h0, *(u32*)&h1);
        }
    } else {
        float4 bb = ((const float4*)b3)[lane];
        float d = g_dni[w];
        a0.x = (a0.x + bb.x) * d; a0.y = (a0.y + bb.y) * d;
        a0.z = (a0.z + bb.z) * d; a0.w = (a0.w + bb.w) * d;
        ((float4*)(of + (size_t)w * D))[lane] = a0;
    }
}

// ---------------- fp16 GEMM via mma.sync, cp.async 2-stage, ldmatrix ----------------
// C[BM/blk, N] = A[.,K] @ Wt[N,K]^T  using A*(Bh + Bl), A fp16 exact
// EPI 0: raw -> fp16 ; 1: bias,deg,LN,PReLU -> fp16
template<int K, int BM, int N, int EPI>
__global__ void __launch_bounds__(256, 1)
k_mmagemm(const __half* __restrict__ A,
          const __half* __restrict__ Bhi, const __half* __restrict__ Blo,
          const float* __restrict__ bias, const float* __restrict__ gam,
          const float* __restrict__ bet, const float* __restrict__ alp,
          __half* __restrict__ Co) {
    extern __shared__ char smem[];
    constexpr int MW = BM / 64;         // warp-rows
    constexpr int NW = N / 64;          // warp-cols
    static_assert(MW * NW == 8, "8 warps");
    constexpr int SA = 80;              // smem row stride (bytes) for 32-half rows
    constexpr int STG = SA * (BM + 2 * N);    // one stage: A, Bh, Bl
    constexpr int OA = 0;
    constexpr int OBH = BM * SA;
    constexpr int OBL = (BM + N) * SA;
    constexpr int POFF = 2 * STG;
    float* pbias = (float*)(smem + POFF);
    float* pgam  = pbias + N;
    float* pbet  = pgam + N;

    const int tid = threadIdx.x;
    const int wid = tid >> 5, lane = tid & 31;
    const int g = lane >> 2, ti = lane & 3;
    const int mw = wid / NW, nw = wid % NW;
    const int mbase = blockIdx.x * BM;
    const u32 smem_u = (u32)__cvta_generic_to_shared(smem);

    // ldmatrix per-lane address components
    const int Lb = lane & 15;
    const u32 rA = (u32)(((lane & 7) + 8 * ((lane >> 3) & 1)) * SA + 16 * ((lane >> 4) & 1));
    const u32 rB = (u32)((Lb & 7) * SA + ((Lb >> 3) << 4));

    if (EPI >= 1) {
        for (int i = tid; i < N; i += 256) {
            pbias[i] = bias[i]; pgam[i] = gam[i]; pbet[i] = bet[i];
        }
    }

    float acc[4][8][4];
    #pragma unroll
    for (int t = 0; t < 4; t++)
        #pragma unroll
        for (int j = 0; j < 8; j++)
            #pragma unroll
            for (int q = 0; q < 4; q++) acc[t][j][q] = 0.f;

    auto issue_stage = [&](int it, int buf) {
        const int kb = it * 32;
        char* base = smem + buf * STG;
        #pragma unroll
        for (int i = tid; i < BM * 4; i += 256) {
            int r = i >> 2, q = i & 3;
            int rg = mbase + r; if (rg > NN - 1) rg = NN - 1;
            cpa16(base + OA + r * SA + q * 16, A + (size_t)rg * K + kb + q * 8);
        }
        #pragma unroll
        for (int i = tid; i < N * 4; i += 256) {
            int r = i >> 2, q = i & 3;
            size_t go = (size_t)r * K + kb + q * 8;
            cpa16(base + OBH + r * SA + q * 16, Bhi + go);
            cpa16(base + OBL + r * SA + q * 16, Blo + go);
        }
        asm volatile("cp.async.commit_group;" ::: "memory");
    };

    constexpr int NIT = K / 32;
    issue_stage(0, 0);
    for (int it = 0; it < NIT; it++) {
        const int buf = it & 1;
        if (it + 1 < NIT) {
            issue_stage(it + 1, buf ^ 1);
            asm volatile("cp.async.wait_group 1;" ::: "memory");
        } else {
            asm volatile("cp.async.wait_group 0;" ::: "memory");
        }
        __syncthreads();
        const u32 aA  = smem_u + buf * STG + OA  + (u32)((mw * 64) * SA) + rA;
        const u32 aBh = smem_u + buf * STG + OBH + (u32)((nw * 64) * SA) + rB;
        const u32 aBl = smem_u + buf * STG + OBL + (u32)((nw * 64) * SA) + rB;
        #pragma unroll
        for (int kt = 0; kt < 2; kt++) {
            const u32 kof = kt * 32;
            u32 af[4][4];
            #pragma unroll
            for (int t = 0; t < 4; t++) ldsm4(af[t], aA + (u32)(t * 16 * SA) + kof);
            #pragma unroll
            for (int j = 0; j < 8; j++) {
                u32 bh[2], bl[2];
                ldsm2(bh, aBh + (u32)(j * 8 * SA) + kof);
                ldsm2(bl, aBl + (u32)(j * 8 * SA) + kof);
                #pragma unroll
                for (int t = 0; t < 4; t++) {
                    mma16816(acc[t][j], af[t], bh);
                    mma16816(acc[t][j], af[t], bl);
                }
            }
        }
        __syncthreads();
    }

    if (EPI == 0) {
        #pragma unroll
        for (int t = 0; t < 4; t++) {
            int rl = mbase + mw * 64 + t * 16 + g;
            int rh = rl + 8;
            #pragma unroll
            for (int j = 0; j < 8; j++) {
                int c = nw * 64 + j * 8 + ti * 2;
                if (rl < NN) {
                    __half2 v = __floats2half2_rn(acc[t][j][0], acc[t][j][1]);
                    *(__half2*)(Co + (size_t)rl * N + c) = v;
                }
                if (rh < NN) {
                    __half2 v = __floats2half2_rn(acc[t][j][2], acc[t][j][3]);
                    *(__half2*)(Co + (size_t)rh * N + c) = v;
                }
            }
        }
        return;
    }

    // fused epilogue: v=(acc+bias)*dni; LN; PReLU -> fp16
    float* red = (float*)smem;  // [BM][NW][2], reuses tile smem
    float mul[4], invl[4], muh[4], invh[4];
    #pragma unroll
    for (int t = 0; t < 4; t++) {
        int rloc = mw * 64 + t * 16 + g;
        int rl = mbase + rloc, rh = rl + 8;
        float dl = g_dni[(rl < NN) ? rl : (NN - 1)];
        float dh = g_dni[(rh < NN) ? rh : (NN - 1)];
        float s0 = 0.f, q0 = 0.f, s1 = 0.f, q1 = 0.f;
        #pragma unroll
        for (int j = 0; j < 8; j++) {
            int c = nw * 64 + j * 8 + ti * 2;
            float b0 = pbias[c], b1 = pbias[c + 1];
            float v0 = (acc[t][j][0] + b0) * dl;
            float v1 = (acc[t][j][1] + b1) * dl;
            float v2 = (acc[t][j][2] + b0) * dh;
            float v3 = (acc[t][j][3] + b1) * dh;
            acc[t][j][0] = v0; acc[t][j][1] = v1;
            acc[t][j][2] = v2; acc[t][j][3] = v3;
            s0 += v0 + v1; q0 += v0 * v0 + v1 * v1;
            s1 += v2 + v3; q1 += v2 * v2 + v3 * v3;
        }
        #pragma unroll
        for (int o = 1; o <= 2; o <<= 1) {
            s0 += __shfl_xor_sync(0xffffffffu, s0, o);
            q0 += __shfl_xor_sync(0xffffffffu, q0, o);
            s1 += __shfl_xor_sync(0xffffffffu, s1, o);
            q1 += __shfl_xor_sync(0xffffffffu, q1, o);
        }
        if (ti == 0) {
            red[(rloc * NW + nw) * 2 + 0] = s0;
            red[(rloc * NW + nw) * 2 + 1] = q0;
            red[((rloc + 8) * NW + nw) * 2 + 0] = s1;
            red[((rloc + 8) * NW + nw) * 2 + 1] = q1;
        }
    }
    __syncthreads();
    #pragma unroll
    for (int t = 0; t < 4; t++) {
        int rloc = mw * 64 + t * 16 + g;
        float s0 = 0.f, q0 = 0.f, s1 = 0.f, q1 = 0.f;
        #pragma unroll
        for (int k = 0; k < NW; k++) {
            s0 += red[(rloc * NW + k) * 2 + 0];
            q0 += red[(rloc * NW + k) * 2 + 1];
            s1 += red[((rloc + 8) * NW + k) * 2 + 0];
            q1 += red[((rloc + 8) * NW + k) * 2 + 1];
        }
        float m0 = s0 * (1.0f / N), m1 = s1 * (1.0f / N);
        mul[t] = m0; muh[t] = m1;
        invl[t] = rsqrtf(q0 * (1.0f / N) - m0 * m0 + 1e-5f);
        invh[t] = rsqrtf(q1 * (1.0f / N) - m1 * m1 + 1e-5f);
    }
    const float alpha = __ldg(alp);
    #pragma unroll
    for (int t = 0; t < 4; t++) {
        int rl = mbase + mw * 64 + t * 16 + g;
        int rh = rl + 8;
        #pragma unroll
        for (int j = 0; j < 8; j++) {
            int c = nw * 64 + j * 8 + ti * 2;
            float g0 = pgam[c], g1 = pgam[c + 1];
            float e0 = pbet[c], e1 = pbet[c + 1];
            float y0 = g0 * (acc[t][j][0] - mul[t]) * invl[t] + e0;
            float y1 = g1 * (acc[t][j][1] - mul[t]) * invl[t] + e1;
            float y2 = g0 * (acc[t][j][2] - muh[t]) * invh[t] + e0;
            float y3 = g1 * (acc[t][j][3] - muh[t]) * invh[t] + e1;
            y0 = (y0 >= 0.f) ? y0 : alpha * y0;
            y1 = (y1 >= 0.f) ? y1 : alpha * y1;
            y2 = (y2 >= 0.f) ? y2 : alpha * y2;
            y3 = (y3 >= 0.f) ? y3 : alpha * y3;
            if (rl < NN)
                *(__half2*)(Co + (size_t)rl * N + c) = __floats2half2_rn(y0, y1);
            if (rh < NN)
                *(__half2*)(Co + (size_t)rh * N + c) = __floats2half2_rn(y2, y3);
        }
    }
}

// ---------------- launch ----------------
extern "C" void kernel_launch(void* const* d_in, const int* in_sizes, int n_in,
                              void* d_out, int out_size) {
    const float* feat = (const float*)d_in[0];
    const float* W1 = (const float*)d_in[1];  const float* b1 = (const float*)d_in[2];
    const float* g1 = (const float*)d_in[3];  const float* be1 = (const float*)d_in[4];
    const float* a1 = (const float*)d_in[5];
    const float* W2 = (const float*)d_in[6];  const float* b2 = (const float*)d_in[7];
    const float* g2 = (const float*)d_in[8];  const float* be2 = (const float*)d_in[9];
    const float* a2 = (const float*)d_in[10];
    const float* W3 = (const float*)d_in[11]; const float* b3 = (const float*)d_in[12];
    const int* src = (const int*)d_in[13];
    const int* dst = (const int*)d_in[14];
    float* out = (float*)d_out;

    void* p;
    cudaGetSymbolAddress(&p, g_f16);   __half* f16 = (__half*)p;
    cudaGetSymbolAddress(&p, g_a16);   __half* a16 = (__half*)p;
    cudaGetSymbolAddress(&p, g_hh);    __half* hh = (__half*)p;
    cudaGetSymbolAddress(&p, g_p16);   __half* p16 = (__half*)p;
    cudaGetSymbolAddress(&p, g_q16);   __half* q16 = (__half*)p;
    cudaGetSymbolAddress(&p, g_w1h);   __half* w1h = (__half*)p;
    cudaGetSymbolAddress(&p, g_w1l);   __half* w1l = (__half*)p;
    cudaGetSymbolAddress(&p, g_w2h);   __half* w2h = (__half*)p;
    cudaGetSymbolAddress(&p, g_w2l);   __half* w2l = (__half*)p;
    cudaGetSymbolAddress(&p, g_w3h);   __half* w3h = (__half*)p;
    cudaGetSymbolAddress(&p, g_w3l);   __half* w3l = (__half*)p;

    // smem: 2 stages of 80*(BM+2N) + 3*N floats params
    constexpr int SM1 = 2 * 80 * (128 + 2 * 256) + 3 * 256 * 4;  // 105472
    constexpr int SM3 = 2 * 80 * (256 + 2 * 128) + 3 * 128 * 4;  // 83456
    cudaFuncSetAttribute(k_mmagemm<128, 128, 256, 1>, cudaFuncAttributeMaxDynamicSharedMemorySize, SM1);
    cudaFuncSetAttribute(k_mmagemm<256, 128, 256, 1>, cudaFuncAttributeMaxDynamicSharedMemorySize, SM1);
    cudaFuncSetAttribute(k_mmagemm<256, 256, 128, 0>, cudaFuncAttributeMaxDynamicSharedMemorySize, SM3);

    // degree + CSR
    k_zero<<<(NN + 255) / 256, 256>>>();
    k_deg<<<(EE + 255) / 256, 256>>>(src, dst);
    k_norm<<<(NN + 255) / 256, 256>>>();
    k_part<<<NSB, 256>>>();
    k_pscan<<<1, 128>>>();
    k_scat<<<NSB, 1024>>>();
    k_fill<<<(EE + 255) / 256, 256>>>(src, dst);

    // weight transpose + fp16 split ; feat -> fp16
    k_wsplit<<<(128 * 256 + 255) / 256, 256>>>(W1, w1h, w1l, 128, 256);
    k_wsplit<<<(256 * 256 + 255) / 256, 256>>>(W2, w2h, w2l, 256, 256);
    k_wsplit<<<(256 * 128 + 255) / 256, 256>>>(W3, w3h, w3l, 256, 128);
    k_cvt16<<<(NN * 128 / 4 + 255) / 256, 256>>>(feat, f16, NN * 128 / 4);

    // layer 1: agg(feat16) -> fp16 ; GEMM 128->256 + LN epilogue -> fp16
    k_agg<128, 1><<<(NN + 7) / 8, 256>>>(f16, a16, nullptr, nullptr);
    k_mmagemm<128, 128, 256, 1><<<(NN + 127) / 128, 256, SM1>>>(
        a16, w1h, w1l, b1, g1, be1, a1, hh);

    // layer 2: agg(fp16) -> fp16 ; GEMM 256->256 + LN epilogue -> fp16
    k_agg<256, 1><<<(NN + 7) / 8, 256>>>(hh, a16, nullptr, nullptr);
    k_mmagemm<256, 128, 256, 1><<<(NN + 127) / 128, 256, SM1>>>(
        a16, w2h, w2l, b2, g2, be2, a2, p16);

    // layer 3: GEMM 256->128 raw -> fp16 ; agg final (fp16 gather) with (x+b3)*deg_in
    k_mmagemm<256, 256, 128, 0><<<(NN + 255) / 256, 256, SM3>>>(
        p16, w3h, w3l, nullptr, nullptr, nullptr, nullptr, q16);
    k_agg<128, 2><<<(NN + 7) / 8, 256>>>(q16, nullptr, out, b3);
}

// round 7
// speedup vs baseline: 2.5944x; 1.2063x over previous
#include <cuda_runtime.h>
#include <cuda_fp16.h>
#include <cstdint>

#define NN 100000
#define EE 1600000
#define NSB 98            // ceil(NN/1024)
typedef unsigned long long u64;
typedef unsigned int u32;

// ---------------- device scratch ----------------
__device__ __half g_f16[(size_t)NN * 128];    // feat fp16
__device__ __half g_a16[(size_t)NN * 256];    // agg output fp16
__device__ __half g_hh[(size_t)NN * 256];     // L1 gemm out fp16
__device__ __half g_p16[(size_t)NN * 256];    // L2 gemm out fp16
__device__ __half g_q16[(size_t)NN * 128];    // L3 gemm out fp16
__device__ __half g_w1[256 * 128];
__device__ __half g_w2[256 * 256];
__device__ __half g_w3[128 * 256];
__device__ float g_dno[NN], g_dni[NN];
__device__ int g_cout[NN], g_cin[NN];
__device__ int g_ptr[NN + 1], g_cur[NN], g_csrc[EE];
__device__ int g_part[128], g_poff[128];

// ---------------- helpers ----------------
__device__ __forceinline__ void fmah4(float4& a, float w, const uint2 v) {
    __half2 h0 = *(__half2*)&v.x, h1 = *(__half2*)&v.y;
    float2 f0 = __half22float2(h0), f1 = __half22float2(h1);
    a.x = fmaf(w, f0.x, a.x); a.y = fmaf(w, f0.y, a.y);
    a.z = fmaf(w, f1.x, a.z); a.w = fmaf(w, f1.y, a.w);
}
__device__ __forceinline__ void mma16816(float* c, const u32* a, const u32* b) {
    asm volatile(
        "mma.sync.aligned.m16n8k16.row.col.f32.f16.f16.f32 "
        "{%0,%1,%2,%3},{%4,%5,%6,%7},{%8,%9},{%0,%1,%2,%3};"
        : "+f"(c[0]), "+f"(c[1]), "+f"(c[2]), "+f"(c[3])
        : "r"(a[0]), "r"(a[1]), "r"(a[2]), "r"(a[3]), "r"(b[0]), "r"(b[1]));
}
__device__ __forceinline__ void cpa16(void* s, const void* g) {
    u32 sa = (u32)__cvta_generic_to_shared(s);
    asm volatile("cp.async.cg.shared.global [%0], [%1], 16;" :: "r"(sa), "l"(g));
}
__device__ __forceinline__ void ldsm4(u32* r, u32 a) {
    asm volatile("ldmatrix.sync.aligned.m8n8.x4.shared.b16 {%0,%1,%2,%3},[%4];"
                 : "=r"(r[0]), "=r"(r[1]), "=r"(r[2]), "=r"(r[3]) : "r"(a));
}
__device__ __forceinline__ void ldsm2(u32* r, u32 a) {
    asm volatile("ldmatrix.sync.aligned.m8n8.x2.shared.b16 {%0,%1},[%2];"
                 : "=r"(r[0]), "=r"(r[1]) : "r"(a));
}

// ---------------- prep ----------------
__global__ void k_zero() {
    int i = blockIdx.x * blockDim.x + threadIdx.x;
    if (i < NN) { g_cout[i] = 0; g_cin[i] = 0; }
}
__global__ void k_deg(const int* __restrict__ src, const int* __restrict__ dst) {
    int i = blockIdx.x * blockDim.x + threadIdx.x;
    if (i < EE) {
        atomicAdd(&g_cout[src[i]], 1);
        atomicAdd(&g_cin[dst[i]], 1);
    }
}
__global__ void k_norm() {
    int i = blockIdx.x * blockDim.x + threadIdx.x;
    if (i < NN) {
        int co = g_cout[i]; if (co < 1) co = 1;
        int ci = g_cin[i];  if (ci < 1) ci = 1;
        g_dno[i] = rsqrtf((float)co);
        g_dni[i] = rsqrtf((float)ci);
    }
}
__global__ void k_part() {
    int b = blockIdx.x, tid = threadIdx.x;
    int s = 0;
    for (int j = tid; j < 1024; j += 256) {
        int i = b * 1024 + j;
        s += (i < NN) ? g_cin[i] : 0;
    }
    #pragma unroll
    for (int o = 16; o; o >>= 1) s += __shfl_xor_sync(0xffffffffu, s, o);
    __shared__ int sh[8];
    if ((tid & 31) == 0) sh[tid >> 5] = s;
    __syncthreads();
    if (tid == 0) {
        int t = 0;
        #pragma unroll
        for (int j = 0; j < 8; j++) t += sh[j];
        g_part[b] = t;
    }
}
__global__ void k_pscan() {
    __shared__ int ws[4], ws2[4];
    int tid = threadIdx.x, lane = tid & 31, w = tid >> 5;
    int v = (tid < NSB) ? g_part[tid] : 0;
    int x = v;
    #pragma unroll
    for (int o = 1; o < 32; o <<= 1) {
        int t = __shfl_up_sync(0xffffffffu, x, o);
        if (lane >= o) x += t;
    }
    if (lane == 31) ws[w] = x;
    __syncthreads();
    if (tid == 0) {
        int run = 0;
        #pragma unroll
        for (int j = 0; j < 4; j++) { ws2[j] = run; run += ws[j]; }
    }
    __syncthreads();
    if (tid < NSB) g_poff[tid] = ws2[w] + x - v;
}
__global__ void k_scat() {
    __shared__ int ws[32];
    int b = blockIdx.x, tid = threadIdx.x;
    int lane = tid & 31, w = tid >> 5;
    int i = b * 1024 + tid;
    int v = (i < NN) ? g_cin[i] : 0;
    int x = v;
    #pragma unroll
    for (int o = 1; o < 32; o <<= 1) {
        int t = __shfl_up_sync(0xffffffffu, x, o);
        if (lane >= o) x += t;
    }
    if (lane == 31) ws[w] = x;
    __syncthreads();
    if (w == 0) {
        int s = ws[lane];
        #pragma unroll
        for (int o = 1; o < 32; o <<= 1) {
            int t = __shfl_up_sync(0xffffffffu, s, o);
            if (lane >= o) s += t;
        }
        ws[lane] = s;
    }
    __syncthreads();
    int pre = (w > 0) ? ws[w - 1] : 0;
    int exc = g_poff[b] + pre + x - v;
    if (i < NN) { g_ptr[i] = exc; g_cur[i] = exc; }
    if (b == 0 && tid == 0) g_ptr[NN] = EE;
}
__global__ void k_fill(const int* __restrict__ src, const int* __restrict__ dst) {
    int i = blockIdx.x * blockDim.x + threadIdx.x;
    if (i < EE) {
        int d = dst[i];
        int p = atomicAdd(&g_cur[d], 1);
        g_csrc[p] = src[i];
    }
}
// transpose weights to fp16: W[K,Nout] -> Wt[Nout,K]
__global__ void k_wtr(const float* __restrict__ W, __half* __restrict__ H,
                      int Kd, int Nout) {
    int i = blockIdx.x * blockDim.x + threadIdx.x;
    if (i < Kd * Nout) {
        int n = i / Kd, k = i % Kd;
        H[i] = __float2half_rn(W[(size_t)k * Nout + n]);
    }
}
// f32 -> fp16 conversion (vectorized)
__global__ void k_cvt16(const float* __restrict__ in, __half* __restrict__ out, int n4) {
    int i = blockIdx.x * blockDim.x + threadIdx.x;
    if (i < n4) {
        float4 v = ((const float4*)in)[i];
        __half2 a = __floats2half2_rn(v.x, v.y), b = __floats2half2_rn(v.z, v.w);
        ((uint2*)out)[i] = make_uint2(*(u32*)&a, *(u32*)&b);
    }
}

// ---------------- aggregation (warp-per-node, CSR, fp16 gather) ----------------
// MODE 1: write fp16; MODE 2: (acc+b3)*dni -> f32 out
template<int D, int MODE>
__global__ void k_agg(const __half* __restrict__ in,
                      __half* __restrict__ oh, float* __restrict__ of,
                      const float* __restrict__ b3) {
    const int w = (blockIdx.x << 3) + (threadIdx.x >> 5);
    const int lane = threadIdx.x & 31;
    if (w >= NN) return;
    const int beg = g_ptr[w], end = g_ptr[w + 1];
    float4 a0 = make_float4(0.f, 0.f, 0.f, 0.f);
    float4 a1 = make_float4(0.f, 0.f, 0.f, 0.f);

    int e = beg;
    for (; e + 4 <= end; e += 4) {
        int s0 = g_csrc[e], s1 = g_csrc[e + 1];
        int s2 = g_csrc[e + 2], s3 = g_csrc[e + 3];
        float w0 = g_dno[s0], w1 = g_dno[s1];
        float w2 = g_dno[s2], w3 = g_dno[s3];
        const uint2* r0 = (const uint2*)(in + (size_t)s0 * D);
        const uint2* r1 = (const uint2*)(in + (size_t)s1 * D);
        const uint2* r2 = (const uint2*)(in + (size_t)s2 * D);
        const uint2* r3 = (const uint2*)(in + (size_t)s3 * D);
        uint2 v0 = r0[lane], v1 = r1[lane], v2 = r2[lane], v3 = r3[lane];
        fmah4(a0, w0, v0); fmah4(a0, w1, v1); fmah4(a0, w2, v2); fmah4(a0, w3, v3);
        if (D == 256) {
            uint2 u0 = r0[lane + 32], u1 = r1[lane + 32];
            uint2 u2 = r2[lane + 32], u3 = r3[lane + 32];
            fmah4(a1, w0, u0); fmah4(a1, w1, u1); fmah4(a1, w2, u2); fmah4(a1, w3, u3);
        }
    }
    for (; e < end; e++) {
        int s0 = g_csrc[e];
        float w0 = g_dno[s0];
        const uint2* r0 = (const uint2*)(in + (size_t)s0 * D);
        fmah4(a0, w0, r0[lane]);
        if (D == 256) fmah4(a1, w0, r0[lane + 32]);
    }
    if (MODE == 1) {
        __half2 h0 = __floats2half2_rn(a0.x, a0.y), h1 = __floats2half2_rn(a0.z, a0.w);
        ((uint2*)(oh + (size_t)w * D))[lane] = make_uint2(*(u32*)&h0, *(u32*)&h1);
        if (D == 256) {
            h0 = __floats2half2_rn(a1.x, a1.y); h1 = __floats2half2_rn(a1.z, a1.w);
            ((uint2*)(oh + (size_t)w * D))[lane + 32] = make_uint2(*(u32*)&h0, *(u32*)&h1);
        }
    } else {
        float4 bb = ((const float4*)b3)[lane];
        float d = g_dni[w];
        a0.x = (a0.x + bb.x) * d; a0.y = (a0.y + bb.y) * d;
        a0.z = (a0.z + bb.z) * d; a0.w = (a0.w + bb.w) * d;
        ((float4*)(of + (size_t)w * D))[lane] = a0;
    }
}

// ---------------- fp16 GEMM via mma.sync, cp.async 3-stage, ldmatrix ----------------
// C[BM/blk, N] = A[.,K] @ Wt[N,K]^T, all fp16, fp32 accum
// EPI 0: raw -> fp16 ; 1: bias,deg,LN,PReLU -> fp16
template<int K, int BM, int N, int EPI>
__global__ void __launch_bounds__(256, 1)
k_mmagemm(const __half* __restrict__ A, const __half* __restrict__ B,
          const float* __restrict__ bias, const float* __restrict__ gam,
          const float* __restrict__ bet, const float* __restrict__ alp,
          __half* __restrict__ Co) {
    extern __shared__ char smem[];
    constexpr int MW = BM / 64;         // warp-rows
    constexpr int NW = N / 64;          // warp-cols
    static_assert(MW * NW == 8, "8 warps");
    constexpr int SA = 80;              // smem row stride (bytes) for 32-half rows
    constexpr int STG = SA * (BM + N);  // one stage: A,B
    constexpr int OA = 0;
    constexpr int OB = BM * SA;
    constexpr int NS = 3;
    constexpr int POFF = NS * STG;
    float* pbias = (float*)(smem + POFF);
    float* pgam  = pbias + N;
    float* pbet  = pgam + N;

    const int tid = threadIdx.x;
    const int wid = tid >> 5, lane = tid & 31;
    const int g = lane >> 2, ti = lane & 3;
    const int mw = wid / NW, nw = wid % NW;
    const int mbase = blockIdx.x * BM;
    const u32 smem_u = (u32)__cvta_generic_to_shared(smem);

    // ldmatrix per-lane address components
    const int Lb = lane & 15;
    const u32 rA = (u32)(((lane & 7) + 8 * ((lane >> 3) & 1)) * SA + 16 * ((lane >> 4) & 1));
    const u32 rB = (u32)((Lb & 7) * SA + ((Lb >> 3) << 4));

    if (EPI >= 1) {
        for (int i = tid; i < N; i += 256) {
            pbias[i] = bias[i]; pgam[i] = gam[i]; pbet[i] = bet[i];
        }
    }

    float acc[4][8][4];
    #pragma unroll
    for (int t = 0; t < 4; t++)
        #pragma unroll
        for (int j = 0; j < 8; j++)
            #pragma unroll
            for (int q = 0; q < 4; q++) acc[t][j][q] = 0.f;

    auto issue_stage = [&](int it, int buf) {
        const int kb = it * 32;
        char* base = smem + buf * STG;
        #pragma unroll
        for (int i = tid; i < BM * 4; i += 256) {
            int r = i >> 2, q = i & 3;
            int rg = mbase + r; if (rg > NN - 1) rg = NN - 1;
            cpa16(base + OA + r * SA + q * 16, A + (size_t)rg * K + kb + q * 8);
        }
        #pragma unroll
        for (int i = tid; i < N * 4; i += 256) {
            int r = i >> 2, q = i & 3;
            cpa16(base + OB + r * SA + q * 16, B + (size_t)r * K + kb + q * 8);
        }
        asm volatile("cp.async.commit_group;" ::: "memory");
    };

    constexpr int NIT = K / 32;
    issue_stage(0, 0);
    if (NIT > 1) issue_stage(1, 1);
    for (int it = 0; it < NIT; it++) {
        const int buf = it % NS;
        if (it + 2 < NIT) {
            issue_stage(it + 2, (it + 2) % NS);
            asm volatile("cp.async.wait_group 2;" ::: "memory");
        } else if (it + 1 < NIT) {
            asm volatile("cp.async.wait_group 1;" ::: "memory");
        } else {
            asm volatile("cp.async.wait_group 0;" ::: "memory");
        }
        __syncthreads();
        const u32 aA = smem_u + buf * STG + OA + (u32)((mw * 64) * SA) + rA;
        const u32 aB = smem_u + buf * STG + OB + (u32)((nw * 64) * SA) + rB;
        #pragma unroll
        for (int kt = 0; kt < 2; kt++) {
            const u32 kof = kt * 32;
            u32 af[4][4];
            #pragma unroll
            for (int t = 0; t < 4; t++) ldsm4(af[t], aA + (u32)(t * 16 * SA) + kof);
            #pragma unroll
            for (int j = 0; j < 8; j++) {
                u32 bf[2];
                ldsm2(bf, aB + (u32)(j * 8 * SA) + kof);
                #pragma unroll
                for (int t = 0; t < 4; t++) mma16816(acc[t][j], af[t], bf);
            }
        }
        __syncthreads();
    }

    if (EPI == 0) {
        #pragma unroll
        for (int t = 0; t < 4; t++) {
            int rl = mbase + mw * 64 + t * 16 + g;
            int rh = rl + 8;
            #pragma unroll
            for (int j = 0; j < 8; j++) {
                int c = nw * 64 + j * 8 + ti * 2;
                if (rl < NN) {
                    __half2 v = __floats2half2_rn(acc[t][j][0], acc[t][j][1]);
                    *(__half2*)(Co + (size_t)rl * N + c) = v;
                }
                if (rh < NN) {
                    __half2 v = __floats2half2_rn(acc[t][j][2], acc[t][j][3]);
                    *(__half2*)(Co + (size_t)rh * N + c) = v;
                }
            }
        }
        return;
    }

    // fused epilogue: v=(acc+bias)*dni; LN; PReLU -> fp16
    float* red = (float*)smem;  // [BM][NW][2], reuses tile smem
    float mul[4], invl[4], muh[4], invh[4];
    #pragma unroll
    for (int t = 0; t < 4; t++) {
        int rloc = mw * 64 + t * 16 + g;
        int rl = mbase + rloc, rh = rl + 8;
        float dl = g_dni[(rl < NN) ? rl : (NN - 1)];
        float dh = g_dni[(rh < NN) ? rh : (NN - 1)];
        float s0 = 0.f, q0 = 0.f, s1 = 0.f, q1 = 0.f;
        #pragma unroll
        for (int j = 0; j < 8; j++) {
            int c = nw * 64 + j * 8 + ti * 2;
            float b0 = pbias[c], b1 = pbias[c + 1];
            float v0 = (acc[t][j][0] + b0) * dl;
            float v1 = (acc[t][j][1] + b1) * dl;
            float v2 = (acc[t][j][2] + b0) * dh;
            float v3 = (acc[t][j][3] + b1) * dh;
            acc[t][j][0] = v0; acc[t][j][1] = v1;
            acc[t][j][2] = v2; acc[t][j][3] = v3;
            s0 += v0 + v1; q0 += v0 * v0 + v1 * v1;
            s1 += v2 + v3; q1 += v2 * v2 + v3 * v3;
        }
        #pragma unroll
        for (int o = 1; o <= 2; o <<= 1) {
            s0 += __shfl_xor_sync(0xffffffffu, s0, o);
            q0 += __shfl_xor_sync(0xffffffffu, q0, o);
            s1 += __shfl_xor_sync(0xffffffffu, s1, o);
            q1 += __shfl_xor_sync(0xffffffffu, q1, o);
        }
        if (ti == 0) {
            red[(rloc * NW + nw) * 2 + 0] = s0;
            red[(rloc * NW + nw) * 2 + 1] = q0;
            red[((rloc + 8) * NW + nw) * 2 + 0] = s1;
            red[((rloc + 8) * NW + nw) * 2 + 1] = q1;
        }
    }
    __syncthreads();
    #pragma unroll
    for (int t = 0; t < 4; t++) {
        int rloc = mw * 64 + t * 16 + g;
        float s0 = 0.f, q0 = 0.f, s1 = 0.f, q1 = 0.f;
        #pragma unroll
        for (int k = 0; k < NW; k++) {
            s0 += red[(rloc * NW + k) * 2 + 0];
            q0 += red[(rloc * NW + k) * 2 + 1];
            s1 += red[((rloc + 8) * NW + k) * 2 + 0];
            q1 += red[((rloc + 8) * NW + k) * 2 + 1];
        }
        float m0 = s0 * (1.0f / N), m1 = s1 * (1.0f / N);
        mul[t] = m0; muh[t] = m1;
        invl[t] = rsqrtf(q0 * (1.0f / N) - m0 * m0 + 1e-5f);
        invh[t] = rsqrtf(q1 * (1.0f / N) - m1 * m1 + 1e-5f);
    }
    const float alpha = __ldg(alp);
    #pragma unroll
    for (int t = 0; t < 4; t++) {
        int rl = mbase + mw * 64 + t * 16 + g;
        int rh = rl + 8;
        #pragma unroll
        for (int j = 0; j < 8; j++) {
            int c = nw * 64 + j * 8 + ti * 2;
            float g0 = pgam[c], g1 = pgam[c + 1];
            float e0 = pbet[c], e1 = pbet[c + 1];
            float y0 = g0 * (acc[t][j][0] - mul[t]) * invl[t] + e0;
            float y1 = g1 * (acc[t][j][1] - mul[t]) * invl[t] + e1;
            float y2 = g0 * (acc[t][j][2] - muh[t]) * invh[t] + e0;
            float y3 = g1 * (acc[t][j][3] - muh[t]) * invh[t] + e1;
            y0 = (y0 >= 0.f) ? y0 : alpha * y0;
            y1 = (y1 >= 0.f) ? y1 : alpha * y1;
            y2 = (y2 >= 0.f) ? y2 : alpha * y2;
            y3 = (y3 >= 0.f) ? y3 : alpha * y3;
            if (rl < NN)
                *(__half2*)(Co + (size_t)rl * N + c) = __floats2half2_rn(y0, y1);
            if (rh < NN)
                *(__half2*)(Co + (size_t)rh * N + c) = __floats2half2_rn(y2, y3);
        }
    }
}

// ---------------- launch ----------------
extern "C" void kernel_launch(void* const* d_in, const int* in_sizes, int n_in,
                              void* d_out, int out_size) {
    const float* feat = (const float*)d_in[0];
    const float* W1 = (const float*)d_in[1];  const float* b1 = (const float*)d_in[2];
    const float* g1 = (const float*)d_in[3];  const float* be1 = (const float*)d_in[4];
    const float* a1 = (const float*)d_in[5];
    const float* W2 = (const float*)d_in[6];  const float* b2 = (const float*)d_in[7];
    const float* g2 = (const float*)d_in[8];  const float* be2 = (const float*)d_in[9];
    const float* a2 = (const float*)d_in[10];
    const float* W3 = (const float*)d_in[11]; const float* b3 = (const float*)d_in[12];
    const int* src = (const int*)d_in[13];
    const int* dst = (const int*)d_in[14];
    float* out = (float*)d_out;

    void* p;
    cudaGetSymbolAddress(&p, g_f16);   __half* f16 = (__half*)p;
    cudaGetSymbolAddress(&p, g_a16);   __half* a16 = (__half*)p;
    cudaGetSymbolAddress(&p, g_hh);    __half* hh = (__half*)p;
    cudaGetSymbolAddress(&p, g_p16);   __half* p16 = (__half*)p;
    cudaGetSymbolAddress(&p, g_q16);   __half* q16 = (__half*)p;
    cudaGetSymbolAddress(&p, g_w1);    __half* w1 = (__half*)p;
    cudaGetSymbolAddress(&p, g_w2);    __half* w2 = (__half*)p;
    cudaGetSymbolAddress(&p, g_w3);    __half* w3 = (__half*)p;

    // smem: 3 stages of 80*(BM+N) + 3*N floats params
    constexpr int SM1 = 3 * 80 * (128 + 256) + 3 * 256 * 4;  // 95232
    constexpr int SM3 = 3 * 80 * (256 + 128) + 3 * 128 * 4;  // 93696
    cudaFuncSetAttribute(k_mmagemm<128, 128, 256, 1>, cudaFuncAttributeMaxDynamicSharedMemorySize, SM1);
    cudaFuncSetAttribute(k_mmagemm<256, 128, 256, 1>, cudaFuncAttributeMaxDynamicSharedMemorySize, SM1);
    cudaFuncSetAttribute(k_mmagemm<256, 256, 128, 0>, cudaFuncAttributeMaxDynamicSharedMemorySize, SM3);

    // degree + CSR
    k_zero<<<(NN + 255) / 256, 256>>>();
    k_deg<<<(EE + 255) / 256, 256>>>(src, dst);
    k_norm<<<(NN + 255) / 256, 256>>>();
    k_part<<<NSB, 256>>>();
    k_pscan<<<1, 128>>>();
    k_scat<<<NSB, 1024>>>();
    k_fill<<<(EE + 255) / 256, 256>>>(src, dst);

    // weight transpose fp16 ; feat -> fp16
    k_wtr<<<(128 * 256 + 255) / 256, 256>>>(W1, w1, 128, 256);
    k_wtr<<<(256 * 256 + 255) / 256, 256>>>(W2, w2, 256, 256);
    k_wtr<<<(256 * 128 + 255) / 256, 256>>>(W3, w3, 256, 128);
    k_cvt16<<<(NN * 128 / 4 + 255) / 256, 256>>>(feat, f16, NN * 128 / 4);

    // layer 1: agg(feat16) -> fp16 ; GEMM 128->256 + LN epilogue -> fp16
    k_agg<128, 1><<<(NN + 7) / 8, 256>>>(f16, a16, nullptr, nullptr);
    k_mmagemm<128, 128, 256, 1><<<(NN + 127) / 128, 256, SM1>>>(
        a16, w1, b1, g1, be1, a1, hh);

    // layer 2: agg(fp16) -> fp16 ; GEMM 256->256 + LN epilogue -> fp16
    k_agg<256, 1><<<(NN + 7) / 8, 256>>>(hh, a16, nullptr, nullptr);
    k_mmagemm<256, 128, 256, 1><<<(NN + 127) / 128, 256, SM1>>>(
        a16, w2, b2, g2, be2, a2, p16);

    // layer 3: GEMM 256->128 raw -> fp16 ; agg final (fp16 gather) with (x+b3)*deg_in
    k_mmagemm<256, 256, 128, 0><<<(NN + 255) / 256, 256, SM3>>>(
        p16, w3, nullptr, nullptr, nullptr, nullptr, q16);
    k_agg<128, 2><<<(NN + 7) / 8, 256>>>(q16, nullptr, out, b3);
}

// round 8
// speedup vs baseline: 2.6693x; 1.0289x over previous
#include <cuda_runtime.h>
#include <cuda_fp16.h>
#include <cstdint>

#define NN 100000
#define EE 1600000
#define NSB 98            // ceil(NN/1024)
typedef unsigned long long u64;
typedef unsigned int u32;

// ---------------- device scratch ----------------
__device__ __half g_f16[(size_t)NN * 128];    // feat fp16
__device__ __half g_a16[(size_t)NN * 256];    // agg output fp16
__device__ __half g_hh[(size_t)NN * 256];     // L1 gemm out fp16
__device__ __half g_p16[(size_t)NN * 256];    // L2 gemm out fp16
__device__ __half g_q16[(size_t)NN * 128];    // L3 gemm out fp16
__device__ __half g_w1[256 * 128];
__device__ __half g_w2[256 * 256];
__device__ __half g_w3[128 * 256];
__device__ float g_dno[NN], g_dni[NN];
__device__ int g_cout[NN], g_cin[NN];
__device__ int g_ptr[NN + 1], g_cur[NN], g_csrc[EE];
__device__ int g_part[128], g_poff[128];

// ---------------- helpers ----------------
__device__ __forceinline__ void fmah4(float4& a, float w, const uint2 v) {
    __half2 h0 = *(__half2*)&v.x, h1 = *(__half2*)&v.y;
    float2 f0 = __half22float2(h0), f1 = __half22float2(h1);
    a.x = fmaf(w, f0.x, a.x); a.y = fmaf(w, f0.y, a.y);
    a.z = fmaf(w, f1.x, a.z); a.w = fmaf(w, f1.y, a.w);
}
__device__ __forceinline__ void mma16816(float* c, const u32* a, const u32* b) {
    asm volatile(
        "mma.sync.aligned.m16n8k16.row.col.f32.f16.f16.f32 "
        "{%0,%1,%2,%3},{%4,%5,%6,%7},{%8,%9},{%0,%1,%2,%3};"
        : "+f"(c[0]), "+f"(c[1]), "+f"(c[2]), "+f"(c[3])
        : "r"(a[0]), "r"(a[1]), "r"(a[2]), "r"(a[3]), "r"(b[0]), "r"(b[1]));
}
__device__ __forceinline__ void cpa16(void* s, const void* g) {
    u32 sa = (u32)__cvta_generic_to_shared(s);
    asm volatile("cp.async.cg.shared.global [%0], [%1], 16;" :: "r"(sa), "l"(g));
}
__device__ __forceinline__ void ldsm4(u32* r, u32 a) {
    asm volatile("ldmatrix.sync.aligned.m8n8.x4.shared.b16 {%0,%1,%2,%3},[%4];"
                 : "=r"(r[0]), "=r"(r[1]), "=r"(r[2]), "=r"(r[3]) : "r"(a));
}
__device__ __forceinline__ void ldsm2(u32* r, u32 a) {
    asm volatile("ldmatrix.sync.aligned.m8n8.x2.shared.b16 {%0,%1},[%2];"
                 : "=r"(r[0]), "=r"(r[1]) : "r"(a));
}

// ---------------- prep ----------------
__global__ void k_zero() {
    int i = blockIdx.x * blockDim.x + threadIdx.x;
    if (i < NN) { g_cout[i] = 0; g_cin[i] = 0; }
}

// fused: degrees (blocks [0,6250)) + weight transposes ([6250,6762)) + feat cvt (rest)
__global__ void k_degmisc(const int* __restrict__ src, const int* __restrict__ dst,
                          const float* __restrict__ W1, const float* __restrict__ W2,
                          const float* __restrict__ W3, const float* __restrict__ feat) {
    const int b = blockIdx.x, tid = threadIdx.x;
    if (b < 6250) {
        int i = b * 256 + tid;
        if (i < EE) {
            atomicAdd(&g_cout[src[i]], 1);
            atomicAdd(&g_cin[dst[i]], 1);
        }
    } else if (b < 6762) {
        int i = (b - 6250) * 256 + tid;   // 0..131071
        if (i < 32768) {
            int n = i / 128, k = i % 128;
            g_w1[i] = __float2half_rn(W1[(size_t)k * 256 + n]);
        } else if (i < 98304) {
            int j = i - 32768;
            int n = j / 256, k = j % 256;
            g_w2[j] = __float2half_rn(W2[(size_t)k * 256 + n]);
        } else {
            int j = i - 98304;
            int n = j / 256, k = j % 256;
            g_w3[j] = __float2half_rn(W3[(size_t)k * 128 + n]);
        }
    } else {
        int i = (b - 6762) * 256 + tid;   // float4 index
        if (i < NN * 128 / 4) {
            float4 v = ((const float4*)feat)[i];
            __half2 a = __floats2half2_rn(v.x, v.y), bb = __floats2half2_rn(v.z, v.w);
            ((uint2*)g_f16)[i] = make_uint2(*(u32*)&a, *(u32*)&bb);
        }
    }
}

// fused: deg norms (blocks [0,391)) + partial sums ([391,489))
__global__ void k_normpart() {
    const int b = blockIdx.x, tid = threadIdx.x;
    if (b < 391) {
        int i = b * 256 + tid;
        if (i < NN) {
            int co = g_cout[i]; if (co < 1) co = 1;
            int ci = g_cin[i];  if (ci < 1) ci = 1;
            g_dno[i] = rsqrtf((float)co);
            g_dni[i] = rsqrtf((float)ci);
        }
    } else {
        int pb = b - 391;
        int s = 0;
        for (int j = tid; j < 1024; j += 256) {
            int i = pb * 1024 + j;
            s += (i < NN) ? g_cin[i] : 0;
        }
        #pragma unroll
        for (int o = 16; o; o >>= 1) s += __shfl_xor_sync(0xffffffffu, s, o);
        __shared__ int sh[8];
        if ((tid & 31) == 0) sh[tid >> 5] = s;
        __syncthreads();
        if (tid == 0) {
            int t = 0;
            #pragma unroll
            for (int j = 0; j < 8; j++) t += sh[j];
            g_part[pb] = t;
        }
    }
}
__global__ void k_pscan() {
    __shared__ int ws[4], ws2[4];
    int tid = threadIdx.x, lane = tid & 31, w = tid >> 5;
    int v = (tid < NSB) ? g_part[tid] : 0;
    int x = v;
    #pragma unroll
    for (int o = 1; o < 32; o <<= 1) {
        int t = __shfl_up_sync(0xffffffffu, x, o);
        if (lane >= o) x += t;
    }
    if (lane == 31) ws[w] = x;
    __syncthreads();
    if (tid == 0) {
        int run = 0;
        #pragma unroll
        for (int j = 0; j < 4; j++) { ws2[j] = run; run += ws[j]; }
    }
    __syncthreads();
    if (tid < NSB) g_poff[tid] = ws2[w] + x - v;
}
__global__ void k_scat() {
    __shared__ int ws[32];
    int b = blockIdx.x, tid = threadIdx.x;
    int lane = tid & 31, w = tid >> 5;
    int i = b * 1024 + tid;
    int v = (i < NN) ? g_cin[i] : 0;
    int x = v;
    #pragma unroll
    for (int o = 1; o < 32; o <<= 1) {
        int t = __shfl_up_sync(0xffffffffu, x, o);
        if (lane >= o) x += t;
    }
    if (lane == 31) ws[w] = x;
    __syncthreads();
    if (w == 0) {
        int s = ws[lane];
        #pragma unroll
        for (int o = 1; o < 32; o <<= 1) {
            int t = __shfl_up_sync(0xffffffffu, s, o);
            if (lane >= o) s += t;
        }
        ws[lane] = s;
    }
    __syncthreads();
    int pre = (w > 0) ? ws[w - 1] : 0;
    int exc = g_poff[b] + pre + x - v;
    if (i < NN) { g_ptr[i] = exc; g_cur[i] = exc; }
    if (b == 0 && tid == 0) g_ptr[NN] = EE;
}
__global__ void k_fill(const int* __restrict__ src, const int* __restrict__ dst) {
    int i = blockIdx.x * blockDim.x + threadIdx.x;
    if (i < EE) {
        int d = dst[i];
        int p = atomicAdd(&g_cur[d], 1);
        g_csrc[p] = src[i];
    }
}

// ---------------- aggregation (warp-per-node, CSR, fp16 gather) ----------------
// MODE 1: write fp16; MODE 2: (acc+b3)*dni -> f32 out
template<int D, int MODE>
__global__ void k_agg(const __half* __restrict__ in,
                      __half* __restrict__ oh, float* __restrict__ of,
                      const float* __restrict__ b3) {
    const int w = (blockIdx.x << 3) + (threadIdx.x >> 5);
    const int lane = threadIdx.x & 31;
    if (w >= NN) return;
    const int beg = g_ptr[w], end = g_ptr[w + 1];
    float4 a0 = make_float4(0.f, 0.f, 0.f, 0.f);
    float4 a1 = make_float4(0.f, 0.f, 0.f, 0.f);

    int e = beg;
    for (; e + 4 <= end; e += 4) {
        int s0 = g_csrc[e], s1 = g_csrc[e + 1];
        int s2 = g_csrc[e + 2], s3 = g_csrc[e + 3];
        float w0 = g_dno[s0], w1 = g_dno[s1];
        float w2 = g_dno[s2], w3 = g_dno[s3];
        const uint2* r0 = (const uint2*)(in + (size_t)s0 * D);
        const uint2* r1 = (const uint2*)(in + (size_t)s1 * D);
        const uint2* r2 = (const uint2*)(in + (size_t)s2 * D);
        const uint2* r3 = (const uint2*)(in + (size_t)s3 * D);
        uint2 v0 = r0[lane], v1 = r1[lane], v2 = r2[lane], v3 = r3[lane];
        fmah4(a0, w0, v0); fmah4(a0, w1, v1); fmah4(a0, w2, v2); fmah4(a0, w3, v3);
        if (D == 256) {
            uint2 u0 = r0[lane + 32], u1 = r1[lane + 32];
            uint2 u2 = r2[lane + 32], u3 = r3[lane + 32];
            fmah4(a1, w0, u0); fmah4(a1, w1, u1); fmah4(a1, w2, u2); fmah4(a1, w3, u3);
        }
    }
    for (; e < end; e++) {
        int s0 = g_csrc[e];
        float w0 = g_dno[s0];
        const uint2* r0 = (const uint2*)(in + (size_t)s0 * D);
        fmah4(a0, w0, r0[lane]);
        if (D == 256) fmah4(a1, w0, r0[lane + 32]);
    }
    if (MODE == 1) {
        __half2 h0 = __floats2half2_rn(a0.x, a0.y), h1 = __floats2half2_rn(a0.z, a0.w);
        ((uint2*)(oh + (size_t)w * D))[lane] = make_uint2(*(u32*)&h0, *(u32*)&h1);
        if (D == 256) {
            h0 = __floats2half2_rn(a1.x, a1.y); h1 = __floats2half2_rn(a1.z, a1.w);
            ((uint2*)(oh + (size_t)w * D))[lane + 32] = make_uint2(*(u32*)&h0, *(u32*)&h1);
        }
    } else {
        float4 bb = ((const float4*)b3)[lane];
        float d = g_dni[w];
        a0.x = (a0.x + bb.x) * d; a0.y = (a0.y + bb.y) * d;
        a0.z = (a0.z + bb.z) * d; a0.w = (a0.w + bb.w) * d;
        ((float4*)(of + (size_t)w * D))[lane] = a0;
    }
}

// ---------------- fp16 GEMM: mma.sync, cp.async 3-stage, ldmatrix, 2 CTA/SM -----
// Warp tile 32x64 (acc 64 f32/thread). C[BM, N] = A[.,K] @ Wt[N,K]^T
// EPI 0: raw -> fp16 ; 1: bias,deg,LN,PReLU -> fp16
template<int K, int BM, int N, int EPI>
__global__ void __launch_bounds__(256, 2)
k_mmagemm(const __half* __restrict__ A, const __half* __restrict__ B,
          const float* __restrict__ bias, const float* __restrict__ gam,
          const float* __restrict__ bet, const float* __restrict__ alp,
          __half* __restrict__ Co) {
    extern __shared__ char smem[];
    constexpr int MW = BM / 32;         // warp-rows (32 rows each)
    constexpr int NW = N / 64;          // warp-cols (64 cols each)
    static_assert(MW * NW == 8, "8 warps");
    constexpr int SA = 80;              // smem row stride (bytes) for 32-half rows
    constexpr int STG = SA * (BM + N);  // one stage: A,B
    constexpr int OA = 0;
    constexpr int OB = BM * SA;
    constexpr int NS = 3;
    constexpr int POFF = NS * STG;
    float* pbias = (float*)(smem + POFF);
    float* pgam  = pbias + N;
    float* pbet  = pgam + N;

    const int tid = threadIdx.x;
    const int wid = tid >> 5, lane = tid & 31;
    const int g = lane >> 2, ti = lane & 3;
    const int mw = wid / NW, nw = wid % NW;
    const int mbase = blockIdx.x * BM;
    const u32 smem_u = (u32)__cvta_generic_to_shared(smem);

    // ldmatrix per-lane address components
    const int Lb = lane & 15;
    const u32 rA = (u32)(((lane & 7) + 8 * ((lane >> 3) & 1)) * SA + 16 * ((lane >> 4) & 1));
    const u32 rB = (u32)((Lb & 7) * SA + ((Lb >> 3) << 4));

    if (EPI >= 1) {
        for (int i = tid; i < N; i += 256) {
            pbias[i] = bias[i]; pgam[i] = gam[i]; pbet[i] = bet[i];
        }
    }

    float acc[2][8][4];
    #pragma unroll
    for (int t = 0; t < 2; t++)
        #pragma unroll
        for (int j = 0; j < 8; j++)
            #pragma unroll
            for (int q = 0; q < 4; q++) acc[t][j][q] = 0.f;

    auto issue_stage = [&](int it, int buf) {
        const int kb = it * 32;
        char* base = smem + buf * STG;
        #pragma unroll
        for (int i = tid; i < BM * 4; i += 256) {
            int r = i >> 2, q = i & 3;
            int rg = mbase + r; if (rg > NN - 1) rg = NN - 1;
            cpa16(base + OA + r * SA + q * 16, A + (size_t)rg * K + kb + q * 8);
        }
        #pragma unroll
        for (int i = tid; i < N * 4; i += 256) {
            int r = i >> 2, q = i & 3;
            cpa16(base + OB + r * SA + q * 16, B + (size_t)r * K + kb + q * 8);
        }
        asm volatile("cp.async.commit_group;" ::: "memory");
    };

    constexpr int NIT = K / 32;
    issue_stage(0, 0);
    if (NIT > 1) issue_stage(1, 1);
    for (int it = 0; it < NIT; it++) {
        const int buf = it % NS;
        if (it + 2 < NIT) {
            issue_stage(it + 2, (it + 2) % NS);
            asm volatile("cp.async.wait_group 2;" ::: "memory");
        } else if (it + 1 < NIT) {
            asm volatile("cp.async.wait_group 1;" ::: "memory");
        } else {
            asm volatile("cp.async.wait_group 0;" ::: "memory");
        }
        __syncthreads();
        const u32 aA = smem_u + buf * STG + OA + (u32)((mw * 32) * SA) + rA;
        const u32 aB = smem_u + buf * STG + OB + (u32)((nw * 64) * SA) + rB;
        #pragma unroll
        for (int kt = 0; kt < 2; kt++) {
            const u32 kof = kt * 32;
            u32 af[2][4];
            #pragma unroll
            for (int t = 0; t < 2; t++) ldsm4(af[t], aA + (u32)(t * 16 * SA) + kof);
            #pragma unroll
            for (int j = 0; j < 8; j++) {
                u32 bf[2];
                ldsm2(bf, aB + (u32)(j * 8 * SA) + kof);
                #pragma unroll
                for (int t = 0; t < 2; t++) mma16816(acc[t][j], af[t], bf);
            }
        }
        __syncthreads();
    }

    if (EPI == 0) {
        #pragma unroll
        for (int t = 0; t < 2; t++) {
            int rl = mbase + mw * 32 + t * 16 + g;
            int rh = rl + 8;
            #pragma unroll
            for (int j = 0; j < 8; j++) {
                int c = nw * 64 + j * 8 + ti * 2;
                if (rl < NN) {
                    __half2 v = __floats2half2_rn(acc[t][j][0], acc[t][j][1]);
                    *(__half2*)(Co + (size_t)rl * N + c) = v;
                }
                if (rh < NN) {
                    __half2 v = __floats2half2_rn(acc[t][j][2], acc[t][j][3]);
                    *(__half2*)(Co + (size_t)rh * N + c) = v;
                }
            }
        }
        return;
    }

    // fused epilogue: v=(acc+bias)*dni; LN; PReLU -> fp16
    float* red = (float*)smem;  // [BM][NW][2], reuses tile smem
    float mul[2], invl[2], muh[2], invh[2];
    #pragma unroll
    for (int t = 0; t < 2; t++) {
        int rloc = mw * 32 + t * 16 + g;
        int rl = mbase + rloc, rh = rl + 8;
        float dl = g_dni[(rl < NN) ? rl : (NN - 1)];
        float dh = g_dni[(rh < NN) ? rh : (NN - 1)];
        float s0 = 0.f, q0 = 0.f, s1 = 0.f, q1 = 0.f;
        #pragma unroll
        for (int j = 0; j < 8; j++) {
            int c = nw * 64 + j * 8 + ti * 2;
            float b0 = pbias[c], b1 = pbias[c + 1];
            float v0 = (acc[t][j][0] + b0) * dl;
            float v1 = (acc[t][j][1] + b1) * dl;
            float v2 = (acc[t][j][2] + b0) * dh;
            float v3 = (acc[t][j][3] + b1) * dh;
            acc[t][j][0] = v0; acc[t][j][1] = v1;
            acc[t][j][2] = v2; acc[t][j][3] = v3;
            s0 += v0 + v1; q0 += v0 * v0 + v1 * v1;
            s1 += v2 + v3; q1 += v2 * v2 + v3 * v3;
        }
        #pragma unroll
        for (int o = 1; o <= 2; o <<= 1) {
            s0 += __shfl_xor_sync(0xffffffffu, s0, o);
            q0 += __shfl_xor_sync(0xffffffffu, q0, o);
            s1 += __shfl_xor_sync(0xffffffffu, s1, o);
            q1 += __shfl_xor_sync(0xffffffffu, q1, o);
        }
        if (ti == 0) {
            red[(rloc * NW + nw) * 2 + 0] = s0;
            red[(rloc * NW + nw) * 2 + 1] = q0;
            red[((rloc + 8) * NW + nw) * 2 + 0] = s1;
            red[((rloc + 8) * NW + nw) * 2 + 1] = q1;
        }
    }
    __syncthreads();
    #pragma unroll
    for (int t = 0; t < 2; t++) {
        int rloc = mw * 32 + t * 16 + g;
        float s0 = 0.f, q0 = 0.f, s1 = 0.f, q1 = 0.f;
        #pragma unroll
        for (int k = 0; k < NW; k++) {
            s0 += red[(rloc * NW + k) * 2 + 0];
            q0 += red[(rloc * NW + k) * 2 + 1];
            s1 += red[((rloc + 8) * NW + k) * 2 + 0];
            q1 += red[((rloc + 8) * NW + k) * 2 + 1];
        }
        float m0 = s0 * (1.0f / N), m1 = s1 * (1.0f / N);
        mul[t] = m0; muh[t] = m1;
        invl[t] = rsqrtf(q0 * (1.0f / N) - m0 * m0 + 1e-5f);
        invh[t] = rsqrtf(q1 * (1.0f / N) - m1 * m1 + 1e-5f);
    }
    const float alpha = __ldg(alp);
    #pragma unroll
    for (int t = 0; t < 2; t++) {
        int rl = mbase + mw * 32 + t * 16 + g;
        int rh = rl + 8;
        #pragma unroll
        for (int j = 0; j < 8; j++) {
            int c = nw * 64 + j * 8 + ti * 2;
            float g0 = pgam[c], g1 = pgam[c + 1];
            float e0 = pbet[c], e1 = pbet[c + 1];
            float y0 = g0 * (acc[t][j][0] - mul[t]) * invl[t] + e0;
            float y1 = g1 * (acc[t][j][1] - mul[t]) * invl[t] + e1;
            float y2 = g0 * (acc[t][j][2] - muh[t]) * invh[t] + e0;
            float y3 = g1 * (acc[t][j][3] - muh[t]) * invh[t] + e1;
            y0 = (y0 >= 0.f) ? y0 : alpha * y0;
            y1 = (y1 >= 0.f) ? y1 : alpha * y1;
            y2 = (y2 >= 0.f) ? y2 : alpha * y2;
            y3 = (y3 >= 0.f) ? y3 : alpha * y3;
            if (rl < NN)
                *(__half2*)(Co + (size_t)rl * N + c) = __floats2half2_rn(y0, y1);
            if (rh < NN)
                *(__half2*)(Co + (size_t)rh * N + c) = __floats2half2_rn(y2, y3);
        }
    }
}

// ---------------- launch ----------------
extern "C" void kernel_launch(void* const* d_in, const int* in_sizes, int n_in,
                              void* d_out, int out_size) {
    const float* feat = (const float*)d_in[0];
    const float* W1 = (const float*)d_in[1];  const float* b1 = (const float*)d_in[2];
    const float* g1 = (const float*)d_in[3];  const float* be1 = (const float*)d_in[4];
    const float* a1 = (const float*)d_in[5];
    const float* W2 = (const float*)d_in[6];  const float* b2 = (const float*)d_in[7];
    const float* g2 = (const float*)d_in[8];  const float* be2 = (const float*)d_in[9];
    const float* a2 = (const float*)d_in[10];
    const float* W3 = (const float*)d_in[11]; const float* b3 = (const float*)d_in[12];
    const int* src = (const int*)d_in[13];
    const int* dst = (const int*)d_in[14];
    float* out = (float*)d_out;

    void* p;
    cudaGetSymbolAddress(&p, g_f16);   __half* f16 = (__half*)p;
    cudaGetSymbolAddress(&p, g_a16);   __half* a16 = (__half*)p;
    cudaGetSymbolAddress(&p, g_hh);    __half* hh = (__half*)p;
    cudaGetSymbolAddress(&p, g_p16);   __half* p16 = (__half*)p;
    cudaGetSymbolAddress(&p, g_q16);   __half* q16 = (__half*)p;
    cudaGetSymbolAddress(&p, g_w1);    __half* w1 = (__half*)p;
    cudaGetSymbolAddress(&p, g_w2);    __half* w2 = (__half*)p;
    cudaGetSymbolAddress(&p, g_w3);    __half* w3 = (__half*)p;

    // smem: 3 stages of 80*(BM+N) + 3*N floats params
    constexpr int SM1 = 3 * 80 * (64 + 256) + 3 * 256 * 4;   // 79872
    constexpr int SM3 = 3 * 80 * (128 + 128) + 3 * 128 * 4;  // 62976
    cudaFuncSetAttribute(k_mmagemm<128, 64, 256, 1>, cudaFuncAttributeMaxDynamicSharedMemorySize, SM1);
    cudaFuncSetAttribute(k_mmagemm<256, 64, 256, 1>, cudaFuncAttributeMaxDynamicSharedMemorySize, SM1);
    cudaFuncSetAttribute(k_mmagemm<256, 128, 128, 0>, cudaFuncAttributeMaxDynamicSharedMemorySize, SM3);

    // prep: zero, fused deg+wtr+cvt, fused norm+part, scan chain, fill
    k_zero<<<(NN + 255) / 256, 256>>>();
    k_degmisc<<<19262, 256>>>(src, dst, W1, W2, W3, feat);
    k_normpart<<<489, 256>>>();
    k_pscan<<<1, 128>>>();
    k_scat<<<NSB, 1024>>>();
    k_fill<<<(EE + 255) / 256, 256>>>(src, dst);

    // layer 1: agg(feat16) -> fp16 ; GEMM 128->256 + LN epilogue -> fp16
    k_agg<128, 1><<<(NN + 7) / 8, 256>>>(f16, a16, nullptr, nullptr);
    k_mmagemm<128, 64, 256, 1><<<(NN + 63) / 64, 256, SM1>>>(
        a16, w1, b1, g1, be1, a1, hh);

    // layer 2: agg(fp16) -> fp16 ; GEMM 256->256 + LN epilogue -> fp16
    k_agg<256, 1><<<(NN + 7) / 8, 256>>>(hh, a16, nullptr, nullptr);
    k_mmagemm<256, 64, 256, 1><<<(NN + 63) / 64, 256, SM1>>>(
        a16, w2, b2, g2, be2, a2, p16);

    // layer 3: GEMM 256->128 raw -> fp16 ; agg final (fp16 gather) with (x+b3)*deg_in
    k_mmagemm<256, 128, 128, 0><<<(NN + 127) / 128, 256, SM3>>>(
        p16, w3, nullptr, nullptr, nullptr, nullptr, q16);
    k_agg<128, 2><<<(NN + 7) / 8, 256>>>(q16, nullptr, out, b3);
}